// round 6
// baseline (speedup 1.0000x reference)
#include <cuda_runtime.h>
#include <cuda_bf16.h>
#include <math.h>
#include <stdint.h>

// Problem constants
constexpr int BB   = 2;
constexpr int LL   = 1024;
constexpr int DD   = 768;
constexpr int NLAY = 8;
constexpr int DIN  = 1536;       // 2*D
constexpr int NSS  = 16;
constexpr int DRR  = 48;         // D/16
constexpr int KCC  = 4;
constexpr int TT   = BB * LL;    // 2048 tokens
constexpr int NR   = DRR + 2 * NSS;  // 80

// Chunked scan
constexpr int CH = 8;
constexpr int CS = LL / CH;      // 128
constexpr int NSTATE = BB * DIN * NSS;   // 49152

// fp32 scratch
constexpr size_t O_X   = 0;
constexpr size_t O_RES = O_X   + (size_t)TT * DD;
constexpr size_t O_XZ  = O_RES + (size_t)TT * DD;
constexpr size_t O_XC  = O_XZ  + (size_t)TT * 2 * DIN;
constexpr size_t O_DBC = O_XC  + (size_t)TT * DIN;
constexpr size_t O_DT  = O_DBC + (size_t)TT * NR;
constexpr size_t O_END = O_DT  + (size_t)TT * DIN;
__device__ float g_buf[O_END];

__device__ float g_hend[(size_t)CH * NSTATE];
__device__ float g_P[(size_t)CH * NSTATE];
__device__ float g_hinit[(size_t)CH * NSTATE];

// bf16 hi/lo activation + weight buffers
constexpr size_t NWI = (size_t)NLAY * 2 * DIN * DD;
constexpr size_t NWO = (size_t)NLAY * DD * DIN;
__device__ __nv_bfloat16 g_xn_h[(size_t)TT * DD];
__device__ __nv_bfloat16 g_xn_l[(size_t)TT * DD];
__device__ __nv_bfloat16 g_y_h[(size_t)TT * DIN];
__device__ __nv_bfloat16 g_y_l[(size_t)TT * DIN];
__device__ __nv_bfloat16 g_wi_h[NWI];
__device__ __nv_bfloat16 g_wi_l[NWI];
__device__ __nv_bfloat16 g_wo_h[NWO];
__device__ __nv_bfloat16 g_wo_l[NWO];

// ---------------------------------------------------------------------------
// weight conversion: fp32 -> bf16 hi/lo (once per launch)
// ---------------------------------------------------------------------------
__global__ void cvt_weights_kernel(const float* __restrict__ wi,
                                   const float* __restrict__ wo) {
    size_t i = (size_t)blockIdx.x * 256 + threadIdx.x;
    if (i < NWI) {
        float v = wi[i];
        __nv_bfloat16 h = __float2bfloat16(v);
        g_wi_h[i] = h;
        g_wi_l[i] = __float2bfloat16(v - __bfloat162float(h));
    } else if (i < NWI + NWO) {
        size_t j = i - NWI;
        float v = wo[j];
        __nv_bfloat16 h = __float2bfloat16(v);
        g_wo_h[j] = h;
        g_wo_l[j] = __float2bfloat16(v - __bfloat162float(h));
    }
}

__global__ void init_kernel(const float* __restrict__ xin,
                            float* __restrict__ x, float* __restrict__ res) {
    int i = blockIdx.x * blockDim.x + threadIdx.x;
    if (i < TT * DD) { x[i] = xin[i]; res[i] = 0.f; }
}

// ---------------------------------------------------------------------------
// Per-layer LN -> bf16 hi/lo ; res += x
// ---------------------------------------------------------------------------
__global__ void __launch_bounds__(256)
layer_ln_kernel(const float* __restrict__ x, float* __restrict__ res,
                __nv_bfloat16* __restrict__ xnh, __nv_bfloat16* __restrict__ xnl,
                const float* __restrict__ w, const float* __restrict__ b) {
    int row = blockIdx.x;
    const float* xr = x + (size_t)row * DD;
    float* rr = res + (size_t)row * DD;
    __nv_bfloat16* oh = xnh + (size_t)row * DD;
    __nv_bfloat16* ol = xnl + (size_t)row * DD;
    int tid = threadIdx.x;
    __shared__ float red[256];

    float v0 = xr[tid], v1 = xr[tid + 256], v2 = xr[tid + 512];
    red[tid] = v0 + v1 + v2;
    __syncthreads();
    for (int st = 128; st > 0; st >>= 1) {
        if (tid < st) red[tid] += red[tid + st];
        __syncthreads();
    }
    float mu = red[0] * (1.f / DD);
    __syncthreads();
    float d0 = v0 - mu, d1 = v1 - mu, d2 = v2 - mu;
    red[tid] = d0 * d0 + d1 * d1 + d2 * d2;
    __syncthreads();
    for (int st = 128; st > 0; st >>= 1) {
        if (tid < st) red[tid] += red[tid + st];
        __syncthreads();
    }
    float inv = rsqrtf(red[0] * (1.f / DD) + 1e-5f);
#pragma unroll
    for (int c = 0; c < 3; c++) {
        int i = tid + c * 256;
        float dv = (c == 0 ? d0 : c == 1 ? d1 : d2);
        float v = dv * inv * w[i] + b[i];
        __nv_bfloat16 h = __float2bfloat16(v);
        oh[i] = h;
        ol[i] = __float2bfloat16(v - __bfloat162float(h));
    }
    rr[tid]       += v0;
    rr[tid + 256] += v1;
    rr[tid + 512] += v2;
}

__global__ void __launch_bounds__(256)
final_ln_kernel(const float* __restrict__ x, const float* __restrict__ res,
                const float* __restrict__ w, const float* __restrict__ b,
                float* __restrict__ out) {
    int row = blockIdx.x;
    const float* xr = x + (size_t)row * DD;
    const float* rr = res + (size_t)row * DD;
    float* o = out + (size_t)row * DD;
    int tid = threadIdx.x;
    __shared__ float red[256];

    float v0 = xr[tid] + rr[tid];
    float v1 = xr[tid + 256] + rr[tid + 256];
    float v2 = xr[tid + 512] + rr[tid + 512];
    red[tid] = v0 + v1 + v2;
    __syncthreads();
    for (int st = 128; st > 0; st >>= 1) {
        if (tid < st) red[tid] += red[tid + st];
        __syncthreads();
    }
    float mu = red[0] * (1.f / DD);
    __syncthreads();
    float d0 = v0 - mu, d1 = v1 - mu, d2 = v2 - mu;
    red[tid] = d0 * d0 + d1 * d1 + d2 * d2;
    __syncthreads();
    for (int st = 128; st > 0; st >>= 1) {
        if (tid < st) red[tid] += red[tid + st];
        __syncthreads();
    }
    float inv = rsqrtf(red[0] * (1.f / DD) + 1e-5f);
    o[tid]       = d0 * inv * w[tid]       + b[tid];
    o[tid + 256] = d1 * inv * w[tid + 256] + b[tid + 256];
    o[tid + 512] = d2 * inv * w[tid + 512] + b[tid + 512];
}

// ===========================================================================
// Tensor-core GEMM (bf16 hi/lo, 3-pass): C[M,N] = A[M,K] * W[N,K]^T, fp32 C.
// CTA tile 128x128, BK=32, 128 threads (4 warps: 2M x 2N), warp tile 64x64.
// 3-stage cp.async pipeline, XOR-swizzled 64B-pitch smem. M,N %128, K %32.
// ===========================================================================
__device__ __forceinline__ unsigned smem_u32(const void* p) {
    return (unsigned)__cvta_generic_to_shared(p);
}
__device__ __forceinline__ unsigned swz(int r, int c) {
    return (unsigned)(r * 64) + ((((unsigned)c >> 3) ^ (((unsigned)r >> 1) & 3u)) << 4);
}
__device__ __forceinline__ void ldsm_x4(unsigned* r, unsigned addr) {
    asm volatile("ldmatrix.sync.aligned.m8n8.x4.shared.b16 {%0,%1,%2,%3}, [%4];"
                 : "=r"(r[0]), "=r"(r[1]), "=r"(r[2]), "=r"(r[3]) : "r"(addr));
}
__device__ __forceinline__ void mma_bf16(float* c, const unsigned* a, const unsigned* b) {
    asm volatile(
        "mma.sync.aligned.m16n8k16.row.col.f32.bf16.bf16.f32 "
        "{%0,%1,%2,%3}, {%4,%5,%6,%7}, {%8,%9}, {%0,%1,%2,%3};"
        : "+f"(c[0]), "+f"(c[1]), "+f"(c[2]), "+f"(c[3])
        : "r"(a[0]), "r"(a[1]), "r"(a[2]), "r"(a[3]), "r"(b[0]), "r"(b[1]));
}
__device__ __forceinline__ void cp16(unsigned dst, const void* src) {
    asm volatile("cp.async.cg.shared.global [%0], [%1], 16;" :: "r"(dst), "l"(src));
}

constexpr int STAGE_BYTES = 32768;          // 4 arrays x 8KB
constexpr int NSTAGE = 3;
constexpr int ARR_A_H = 0, ARR_A_L = 8192, ARR_W_H = 16384, ARR_W_L = 24576;

__global__ void __launch_bounds__(128)
gemm_tc2_kernel(const __nv_bfloat16* __restrict__ Ahg,
                const __nv_bfloat16* __restrict__ Alg,
                const __nv_bfloat16* __restrict__ Whg,
                const __nv_bfloat16* __restrict__ Wlg,
                float* __restrict__ C, int ldc, int K) {
    extern __shared__ __align__(16) unsigned char smraw[];
    const unsigned sbase = smem_u32(smraw);

    const int tid  = threadIdx.x;
    const int lane = tid & 31;
    const int warp = tid >> 5;
    const int wm = (warp >> 1) * 64;     // 2 warps along M
    const int wn = (warp & 1) * 64;      // 2 warps along N
    const int m0 = blockIdx.y * 128;
    const int n0 = blockIdx.x * 128;

    // loader: thread t owns row t (0..127); BK=32 -> 64B -> 4x16B chunks
    const int lrow = tid;
    const size_t aoff = (size_t)(m0 + lrow) * K;
    const size_t woff = (size_t)(n0 + lrow) * K;
    unsigned dsto[4];
#pragma unroll
    for (int c = 0; c < 4; c++)
        dsto[c] = (unsigned)(lrow * 64) +
                  (((unsigned)c ^ (((unsigned)lrow >> 1) & 3u)) << 4);

    const int nsteps = K / 32;

    auto load_stage = [&](int buf, int k0) {
        unsigned sb = sbase + buf * STAGE_BYTES;
        const __nv_bfloat16* pa_h = Ahg + aoff + k0;
        const __nv_bfloat16* pa_l = Alg + aoff + k0;
        const __nv_bfloat16* pw_h = Whg + woff + k0;
        const __nv_bfloat16* pw_l = Wlg + woff + k0;
#pragma unroll
        for (int c = 0; c < 4; c++) {
            cp16(sb + ARR_A_H + dsto[c], pa_h + c * 8);
            cp16(sb + ARR_A_L + dsto[c], pa_l + c * 8);
            cp16(sb + ARR_W_H + dsto[c], pw_h + c * 8);
            cp16(sb + ARR_W_L + dsto[c], pw_l + c * 8);
        }
    };

    float acc[4][8][4];
#pragma unroll
    for (int i = 0; i < 4; i++)
#pragma unroll
        for (int j = 0; j < 8; j++)
#pragma unroll
            for (int q = 0; q < 4; q++) acc[i][j][q] = 0.f;

    // prologue: stages 0 and 1
    load_stage(0, 0);
    asm volatile("cp.async.commit_group;");
    load_stage(1, 32);
    asm volatile("cp.async.commit_group;");

    const int arow = wm + (lane & 7) + (lane & 8);
    const int brow = wn + (lane & 7) + ((lane >> 4) << 3);

    for (int s = 0; s < nsteps; s++) {
        asm volatile("cp.async.wait_group 1;");   // stage s resident
        __syncthreads();
        if (s + 2 < nsteps) load_stage((s + 2) % NSTAGE, (s + 2) * 32);
        asm volatile("cp.async.commit_group;");

        const unsigned sb = sbase + (s % NSTAGE) * STAGE_BYTES;
#pragma unroll
        for (int kk = 0; kk < 32; kk += 16) {
            const int acol = kk + ((lane >> 4) << 3);
            const int bcol = kk + (lane & 8);
            unsigned af[4][4];
            unsigned whf[8][2], wlf[8][2];
#pragma unroll
            for (int mi = 0; mi < 4; mi++)
                ldsm_x4(af[mi], sb + ARR_A_H + swz(arow + mi * 16, acol));
#pragma unroll
            for (int nj = 0; nj < 4; nj++) {
                unsigned r[4];
                ldsm_x4(r, sb + ARR_W_H + swz(brow + nj * 16, bcol));
                whf[nj * 2][0] = r[0]; whf[nj * 2][1] = r[1];
                whf[nj * 2 + 1][0] = r[2]; whf[nj * 2 + 1][1] = r[3];
                ldsm_x4(r, sb + ARR_W_L + swz(brow + nj * 16, bcol));
                wlf[nj * 2][0] = r[0]; wlf[nj * 2][1] = r[1];
                wlf[nj * 2 + 1][0] = r[2]; wlf[nj * 2 + 1][1] = r[3];
            }
#pragma unroll
            for (int mi = 0; mi < 4; mi++)
#pragma unroll
                for (int ni = 0; ni < 8; ni++) {
                    mma_bf16(acc[mi][ni], af[mi], whf[ni]);
                    mma_bf16(acc[mi][ni], af[mi], wlf[ni]);
                }
#pragma unroll
            for (int mi = 0; mi < 4; mi++)
                ldsm_x4(af[mi], sb + ARR_A_L + swz(arow + mi * 16, acol));
#pragma unroll
            for (int mi = 0; mi < 4; mi++)
#pragma unroll
                for (int ni = 0; ni < 8; ni++)
                    mma_bf16(acc[mi][ni], af[mi], whf[ni]);
        }
    }

    // epilogue
#pragma unroll
    for (int mi = 0; mi < 4; mi++) {
        int r0 = m0 + wm + mi * 16 + (lane >> 2);
#pragma unroll
        for (int ni = 0; ni < 8; ni++) {
            int c = n0 + wn + ni * 8 + (lane & 3) * 2;
            *(float2*)&C[(size_t)r0 * ldc + c] =
                make_float2(acc[mi][ni][0], acc[mi][ni][1]);
            *(float2*)&C[(size_t)(r0 + 8) * ldc + c] =
                make_float2(acc[mi][ni][2], acc[mi][ni][3]);
        }
    }
}

// ---------------------------------------------------------------------------
// x_proj SIMT GEMM: dbc[TT,80] = xc[TT,DIN] @ Wx[80,DIN]^T
// ---------------------------------------------------------------------------
__global__ void __launch_bounds__(256)
gemm_xproj_kernel(const float* __restrict__ A, const float* __restrict__ W,
                  float* __restrict__ C) {
    __shared__ float As[16][68];
    __shared__ float Ws[16][17];
    const int tid = threadIdx.x;
    const int tx = tid & 15, ty = tid >> 4;
    const int m0 = blockIdx.y * 64, n0 = blockIdx.x * 16;
    const int lrow = tid >> 2;
    const int lq = (tid & 3) * 4;

    float acc[4] = {0.f, 0.f, 0.f, 0.f};

    for (int k0 = 0; k0 < DIN; k0 += 16) {
        float4 av = *(const float4*)(A + (size_t)(m0 + lrow) * DIN + k0 + lq);
        As[lq + 0][lrow] = av.x; As[lq + 1][lrow] = av.y;
        As[lq + 2][lrow] = av.z; As[lq + 3][lrow] = av.w;
        if (tid < 64) {
            int wr = tid >> 2, wq = (tid & 3) * 4;
            float4 wv = *(const float4*)(W + (size_t)(n0 + wr) * DIN + k0 + wq);
            Ws[wq + 0][wr] = wv.x; Ws[wq + 1][wr] = wv.y;
            Ws[wq + 2][wr] = wv.z; Ws[wq + 3][wr] = wv.w;
        }
        __syncthreads();
#pragma unroll
        for (int kk = 0; kk < 16; kk++) {
            float4 a = *(const float4*)(&As[kk][ty * 4]);
            float wv = Ws[kk][tx];
            acc[0] += a.x * wv; acc[1] += a.y * wv;
            acc[2] += a.z * wv; acc[3] += a.w * wv;
        }
        __syncthreads();
    }
#pragma unroll
    for (int i = 0; i < 4; i++)
        C[(size_t)(m0 + ty * 4 + i) * NR + n0 + tx] = acc[i];
}

// ---------------------------------------------------------------------------
// dt GEMM (SIMT, K=48): dt = softplus(dbc[:,:48] @ Wdt^T + bdt)
// ---------------------------------------------------------------------------
__global__ void __launch_bounds__(256)
gemm_dt_kernel(const float* __restrict__ A, int lda,
               const float* __restrict__ W,
               const float* __restrict__ bias,
               float* __restrict__ C, int ldc, int N, int K) {
    __shared__ float As[16][132];
    __shared__ float Ws[16][68];
    const int tid = threadIdx.x;
    const int tx = tid & 15, ty = tid >> 4;
    const int m0 = blockIdx.y * 128, n0 = blockIdx.x * 64;
    const int ar = tid >> 1;
    const int ak = (tid & 1) * 8;
    const int wr = tid >> 2;
    const int wk = (tid & 3) * 4;

    float acc[8][4];
#pragma unroll
    for (int i = 0; i < 8; i++)
#pragma unroll
        for (int j = 0; j < 4; j++) acc[i][j] = 0.f;

    for (int k0 = 0; k0 < K; k0 += 16) {
        const float* ap = A + (size_t)(m0 + ar) * lda + k0 + ak;
        float4 a0 = *(const float4*)(ap);
        float4 a1 = *(const float4*)(ap + 4);
        As[ak + 0][ar] = a0.x; As[ak + 1][ar] = a0.y;
        As[ak + 2][ar] = a0.z; As[ak + 3][ar] = a0.w;
        As[ak + 4][ar] = a1.x; As[ak + 5][ar] = a1.y;
        As[ak + 6][ar] = a1.z; As[ak + 7][ar] = a1.w;
        float4 wv = *(const float4*)(W + (size_t)(n0 + wr) * K + k0 + wk);
        Ws[wk + 0][wr] = wv.x; Ws[wk + 1][wr] = wv.y;
        Ws[wk + 2][wr] = wv.z; Ws[wk + 3][wr] = wv.w;
        __syncthreads();
#pragma unroll
        for (int kk = 0; kk < 16; kk++) {
            float4 av0 = *(const float4*)(&As[kk][ty * 8]);
            float4 av1 = *(const float4*)(&As[kk][ty * 8 + 4]);
            float4 wv0 = *(const float4*)(&Ws[kk][tx * 4]);
            float a[8] = {av0.x, av0.y, av0.z, av0.w, av1.x, av1.y, av1.z, av1.w};
            float w[4] = {wv0.x, wv0.y, wv0.z, wv0.w};
#pragma unroll
            for (int i = 0; i < 8; i++)
#pragma unroll
                for (int j = 0; j < 4; j++)
                    acc[i][j] += a[i] * w[j];
        }
        __syncthreads();
    }
#pragma unroll
    for (int i = 0; i < 8; i++) {
        int m = m0 + ty * 8 + i;
#pragma unroll
        for (int j = 0; j < 4; j++) {
            int n = n0 + tx * 4 + j;
            float v = acc[i][j] + bias[n];
            v = (v > 20.f) ? v : log1pf(__expf(v));
            C[(size_t)m * ldc + n] = v;
        }
    }
}

// ---------------------------------------------------------------------------
// Causal depthwise conv (KC=4, left pad 3) + bias + SiLU, float4 over channels.
// ---------------------------------------------------------------------------
__global__ void __launch_bounds__(256)
conv_kernel(const float* __restrict__ xz, float* __restrict__ xc,
            const float* __restrict__ cw, const float* __restrict__ cb) {
    int idx = blockIdx.x * blockDim.x + threadIdx.x;   // over TT*DIN/4
    if (idx >= TT * DIN / 4) return;
    int c4 = (idx % (DIN / 4)) * 4;
    int tb = idx / (DIN / 4);
    int t = tb % LL;
    int b = tb / LL;
    float4 acc = *(const float4*)(cb + c4);
    float4 w0 = *(const float4*)(cw + (c4 + 0) * KCC);
    float4 w1 = *(const float4*)(cw + (c4 + 1) * KCC);
    float4 w2 = *(const float4*)(cw + (c4 + 2) * KCC);
    float4 w3 = *(const float4*)(cw + (c4 + 3) * KCC);
    const float wk0[4] = {w0.x, w0.y, w0.z, w0.w};
    const float wk1[4] = {w1.x, w1.y, w1.z, w1.w};
    const float wk2[4] = {w2.x, w2.y, w2.z, w2.w};
    const float wk3[4] = {w3.x, w3.y, w3.z, w3.w};
#pragma unroll
    for (int k = 0; k < KCC; k++) {
        int tt = t - (KCC - 1) + k;
        if (tt >= 0) {
            float4 xv = *(const float4*)(
                xz + ((size_t)(b * LL + tt)) * (2 * DIN) + c4);
            acc.x += wk0[k] * xv.x;
            acc.y += wk1[k] * xv.y;
            acc.z += wk2[k] * xv.z;
            acc.w += wk3[k] * xv.w;
        }
    }
    acc.x = acc.x / (1.f + __expf(-acc.x));
    acc.y = acc.y / (1.f + __expf(-acc.y));
    acc.z = acc.z / (1.f + __expf(-acc.z));
    acc.w = acc.w / (1.f + __expf(-acc.w));
    *(float4*)(xc + (size_t)tb * DIN + c4) = acc;
}

// ===========================================================================
// Chunked selective scan (3 phases).
// ===========================================================================
__global__ void __launch_bounds__(256)
scan_p1_kernel(const float* __restrict__ dt, const float* __restrict__ xc,
               const float* __restrict__ dbc, const float* __restrict__ Alog) {
    int warp = threadIdx.x >> 5;
    int lane = threadIdx.x & 31;
    int n = lane & 15;
    int dl = lane >> 4;
    constexpr int BLOCKS_PER_B = DIN / 16;
    int b = blockIdx.x / BLOCKS_PER_B;
    int d = (blockIdx.x % BLOCKS_PER_B) * 16 + warp * 2 + dl;
    int c = blockIdx.y;

    float Av = -__expf(Alog[d * NSS + n]);
    float h = 0.f, sdt = 0.f;
    size_t rowbase = (size_t)b * LL + (size_t)c * CS;

    for (int t = 0; t < CS; t++) {
        size_t row = rowbase + t;
        float dtv = dt[row * DIN + d];
        float xv  = xc[row * DIN + d];
        float Bv  = dbc[row * NR + DRR + n];
        sdt += dtv;
        h = __expf(dtv * Av) * h + (dtv * xv) * Bv;
    }
    int idx = (b * DIN + d) * NSS + n;
    g_hend[(size_t)c * NSTATE + idx] = h;
    g_P[(size_t)c * NSTATE + idx]   = __expf(Av * sdt);
}

__global__ void __launch_bounds__(256)
scan_chain_kernel() {
    int i = blockIdx.x * 256 + threadIdx.x;
    if (i >= NSTATE) return;
    float hin = 0.f;
#pragma unroll
    for (int c = 0; c < CH; c++) {
        g_hinit[(size_t)c * NSTATE + i] = hin;
        hin = g_P[(size_t)c * NSTATE + i] * hin + g_hend[(size_t)c * NSTATE + i];
    }
}

__global__ void __launch_bounds__(256)
scan_p2_kernel(const float* __restrict__ dt, const float* __restrict__ xc,
               const float* __restrict__ dbc, const float* __restrict__ xz,
               __nv_bfloat16* __restrict__ yh, __nv_bfloat16* __restrict__ yl,
               const float* __restrict__ Alog, const float* __restrict__ Dp) {
    int warp = threadIdx.x >> 5;
    int lane = threadIdx.x & 31;
    int n = lane & 15;
    int dl = lane >> 4;
    constexpr int BLOCKS_PER_B = DIN / 16;
    int b = blockIdx.x / BLOCKS_PER_B;
    int d = (blockIdx.x % BLOCKS_PER_B) * 16 + warp * 2 + dl;
    int c = blockIdx.y;

    float Av = -__expf(Alog[d * NSS + n]);
    float Dv = Dp[d];
    int idx = (b * DIN + d) * NSS + n;
    float h = g_hinit[(size_t)c * NSTATE + idx];
    size_t rowbase = (size_t)b * LL + (size_t)c * CS;

    for (int t = 0; t < CS; t++) {
        size_t row = rowbase + t;
        float dtv = dt[row * DIN + d];
        float xv  = xc[row * DIN + d];
        float Bv  = dbc[row * NR + DRR + n];
        float Cv  = dbc[row * NR + DRR + NSS + n];
        h = __expf(dtv * Av) * h + (dtv * xv) * Bv;
        float yp = h * Cv;
        yp += __shfl_xor_sync(0xffffffffu, yp, 8);
        yp += __shfl_xor_sync(0xffffffffu, yp, 4);
        yp += __shfl_xor_sync(0xffffffffu, yp, 2);
        yp += __shfl_xor_sync(0xffffffffu, yp, 1);
        if (n == 0) {
            float zv = xz[row * (2 * DIN) + DIN + d];
            float sg = zv / (1.f + __expf(-zv));
            float g = (yp + xv * Dv) * sg;
            __nv_bfloat16 gh = __float2bfloat16(g);
            yh[row * DIN + d] = gh;
            yl[row * DIN + d] = __float2bfloat16(g - __bfloat162float(gh));
        }
    }
}

// ---------------------------------------------------------------------------
// Orchestration
// ---------------------------------------------------------------------------
extern "C" void kernel_launch(void* const* d_in, const int* in_sizes, int n_in,
                              void* d_out, int out_size) {
    const float* x        = (const float*)d_in[0];
    const float* ln_w     = (const float*)d_in[1];
    const float* ln_b     = (const float*)d_in[2];
    const float* in_proj  = (const float*)d_in[3];
    const float* conv_w   = (const float*)d_in[4];
    const float* conv_b   = (const float*)d_in[5];
    const float* x_proj   = (const float*)d_in[6];
    const float* dt_w     = (const float*)d_in[7];
    const float* dt_b     = (const float*)d_in[8];
    const float* A_log    = (const float*)d_in[9];
    const float* D_skip   = (const float*)d_in[10];
    const float* out_proj = (const float*)d_in[11];
    const float* fn_w     = (const float*)d_in[12];
    const float* fn_b     = (const float*)d_in[13];
    float* out = (float*)d_out;

    float* base = nullptr;
    cudaGetSymbolAddress((void**)&base, g_buf);
    float* bx   = base + O_X;
    float* bres = base + O_RES;
    float* bxz  = base + O_XZ;
    float* bxc  = base + O_XC;
    float* bdbc = base + O_DBC;
    float* bdt  = base + O_DT;

    __nv_bfloat16 *xnh, *xnl, *yh, *yl, *wih, *wil, *woh, *wol;
    cudaGetSymbolAddress((void**)&xnh, g_xn_h);
    cudaGetSymbolAddress((void**)&xnl, g_xn_l);
    cudaGetSymbolAddress((void**)&yh,  g_y_h);
    cudaGetSymbolAddress((void**)&yl,  g_y_l);
    cudaGetSymbolAddress((void**)&wih, g_wi_h);
    cudaGetSymbolAddress((void**)&wil, g_wi_l);
    cudaGetSymbolAddress((void**)&woh, g_wo_h);
    cudaGetSymbolAddress((void**)&wol, g_wo_l);

    cudaFuncSetAttribute(gemm_tc2_kernel,
                         cudaFuncAttributeMaxDynamicSharedMemorySize,
                         NSTAGE * STAGE_BYTES);

    cvt_weights_kernel<<<(unsigned)((NWI + NWO + 255) / 256), 256>>>(in_proj, out_proj);
    init_kernel<<<(TT * DD) / 256, 256>>>(x, bx, bres);

    for (int l = 0; l < NLAY; l++) {
        layer_ln_kernel<<<TT, 256>>>(bx, bres, xnh, xnl,
                                     ln_w + (size_t)l * DD, ln_b + (size_t)l * DD);
        // xz = xn @ Wi^T   (2048 x 3072, K=768)
        gemm_tc2_kernel<<<dim3((2 * DIN) / 128, TT / 128), 128,
                          NSTAGE * STAGE_BYTES>>>(
            xnh, xnl,
            wih + (size_t)l * 2 * DIN * DD, wil + (size_t)l * 2 * DIN * DD,
            bxz, 2 * DIN, DD);
        // xc = silu(conv(xi) + cb)
        conv_kernel<<<(TT * DIN / 4) / 256, 256>>>(
            bxz, bxc, conv_w + (size_t)l * DIN * KCC, conv_b + (size_t)l * DIN);
        // dbc = xc @ Wx^T  (2048 x 80, K=1536)
        gemm_xproj_kernel<<<dim3(NR / 16, TT / 64), 256>>>(
            bxc, x_proj + (size_t)l * NR * DIN, bdbc);
        // dt = softplus(dbc[:, :48] @ Wdt^T + bdt)
        gemm_dt_kernel<<<dim3(DIN / 64, TT / 128), 256>>>(
            bdbc, NR, dt_w + (size_t)l * DIN * DRR, dt_b + (size_t)l * DIN,
            bdt, DIN, DIN, DRR);
        // chunked selective scan
        scan_p1_kernel<<<dim3(BB * (DIN / 16), CH), 256>>>(
            bdt, bxc, bdbc, A_log + (size_t)l * DIN * NSS);
        scan_chain_kernel<<<(NSTATE + 255) / 256, 256>>>();
        scan_p2_kernel<<<dim3(BB * (DIN / 16), CH), 256>>>(
            bdt, bxc, bdbc, bxz, yh, yl,
            A_log + (size_t)l * DIN * NSS, D_skip + (size_t)l * DIN);
        // x_next = y @ Wo^T  (2048 x 768, K=1536)
        gemm_tc2_kernel<<<dim3(DD / 128, TT / 128), 128,
                          NSTAGE * STAGE_BYTES>>>(
            yh, yl,
            woh + (size_t)l * DD * DIN, wol + (size_t)l * DD * DIN,
            bx, DD, DIN);
    }

    final_ln_kernel<<<TT, 256>>>(bx, bres, fn_w, fn_b, out);
}

// round 7
// speedup vs baseline: 1.9292x; 1.9292x over previous
#include <cuda_runtime.h>
#include <cuda_bf16.h>
#include <math.h>
#include <stdint.h>

// Problem constants
constexpr int BB   = 2;
constexpr int LL   = 1024;
constexpr int DD   = 768;
constexpr int NLAY = 8;
constexpr int DIN  = 1536;       // 2*D
constexpr int NSS  = 16;
constexpr int DRR  = 48;         // D/16
constexpr int KCC  = 4;
constexpr int TT   = BB * LL;    // 2048 tokens
constexpr int NR   = DRR + 2 * NSS;  // 80

// Chunked scan
constexpr int CH = 16;
constexpr int CS = LL / CH;      // 64
constexpr int NSTATE = BB * DIN * NSS;   // 49152

// x_proj split-K
constexpr int XK = 4;                 // k-chunks
constexpr int XKS = DIN / XK;         // 384

// fp32 scratch
constexpr size_t O_X   = 0;
constexpr size_t O_RES = O_X   + (size_t)TT * DD;
constexpr size_t O_XZ  = O_RES + (size_t)TT * DD;
constexpr size_t O_XC  = O_XZ  + (size_t)TT * 2 * DIN;
constexpr size_t O_DBC = O_XC  + (size_t)TT * DIN;
constexpr size_t O_DT  = O_DBC + (size_t)TT * NR;
constexpr size_t O_END = O_DT  + (size_t)TT * DIN;
__device__ float g_buf[O_END];

__device__ float g_hend[(size_t)CH * NSTATE];
__device__ float g_P[(size_t)CH * NSTATE];
__device__ float g_hinit[(size_t)CH * NSTATE];
__device__ float g_dbc_part[XK][(size_t)TT * NR];

// bf16 hi/lo activation + weight buffers
constexpr size_t NWI = (size_t)NLAY * 2 * DIN * DD;
constexpr size_t NWO = (size_t)NLAY * DD * DIN;
__device__ __nv_bfloat16 g_xn_h[(size_t)TT * DD];
__device__ __nv_bfloat16 g_xn_l[(size_t)TT * DD];
__device__ __nv_bfloat16 g_y_h[(size_t)TT * DIN];
__device__ __nv_bfloat16 g_y_l[(size_t)TT * DIN];
__device__ __nv_bfloat16 g_wi_h[NWI];
__device__ __nv_bfloat16 g_wi_l[NWI];
__device__ __nv_bfloat16 g_wo_h[NWO];
__device__ __nv_bfloat16 g_wo_l[NWO];

// ---------------------------------------------------------------------------
// weight conversion: fp32 -> bf16 hi/lo (once per launch)
// ---------------------------------------------------------------------------
__global__ void cvt_weights_kernel(const float* __restrict__ wi,
                                   const float* __restrict__ wo) {
    size_t i = (size_t)blockIdx.x * 256 + threadIdx.x;
    if (i < NWI) {
        float v = wi[i];
        __nv_bfloat16 h = __float2bfloat16(v);
        g_wi_h[i] = h;
        g_wi_l[i] = __float2bfloat16(v - __bfloat162float(h));
    } else if (i < NWI + NWO) {
        size_t j = i - NWI;
        float v = wo[j];
        __nv_bfloat16 h = __float2bfloat16(v);
        g_wo_h[j] = h;
        g_wo_l[j] = __float2bfloat16(v - __bfloat162float(h));
    }
}

__global__ void init_kernel(const float* __restrict__ xin,
                            float* __restrict__ x, float* __restrict__ res) {
    int i = blockIdx.x * blockDim.x + threadIdx.x;
    if (i < TT * DD) { x[i] = xin[i]; res[i] = 0.f; }
}

// ---------------------------------------------------------------------------
// Warp-shuffle block reduction helper (256 threads / 8 warps)
// ---------------------------------------------------------------------------
__device__ __forceinline__ float block_sum_256(float v, float* red,
                                               int lane, int wid) {
#pragma unroll
    for (int o = 16; o > 0; o >>= 1)
        v += __shfl_xor_sync(0xffffffffu, v, o);
    if (lane == 0) red[wid] = v;
    __syncthreads();
    float t = red[0] + red[1] + red[2] + red[3] +
              red[4] + red[5] + red[6] + red[7];
    return t;
}

// ---------------------------------------------------------------------------
// Per-layer LN -> bf16 hi/lo ; res += x   (one block per token, D=768)
// ---------------------------------------------------------------------------
__global__ void __launch_bounds__(256)
layer_ln_kernel(const float* __restrict__ x, float* __restrict__ res,
                __nv_bfloat16* __restrict__ xnh, __nv_bfloat16* __restrict__ xnl,
                const float* __restrict__ w, const float* __restrict__ b) {
    int row = blockIdx.x;
    const float* xr = x + (size_t)row * DD;
    float* rr = res + (size_t)row * DD;
    __nv_bfloat16* oh = xnh + (size_t)row * DD;
    __nv_bfloat16* ol = xnl + (size_t)row * DD;
    int tid = threadIdx.x;
    int lane = tid & 31, wid = tid >> 5;
    __shared__ float red[8];

    float v0 = xr[tid], v1 = xr[tid + 256], v2 = xr[tid + 512];
    float mu = block_sum_256(v0 + v1 + v2, red, lane, wid) * (1.f / DD);
    __syncthreads();
    float d0 = v0 - mu, d1 = v1 - mu, d2 = v2 - mu;
    float var = block_sum_256(d0 * d0 + d1 * d1 + d2 * d2, red, lane, wid)
                * (1.f / DD);
    float inv = rsqrtf(var + 1e-5f);
#pragma unroll
    for (int c = 0; c < 3; c++) {
        int i = tid + c * 256;
        float dv = (c == 0 ? d0 : c == 1 ? d1 : d2);
        float v = dv * inv * w[i] + b[i];
        __nv_bfloat16 h = __float2bfloat16(v);
        oh[i] = h;
        ol[i] = __float2bfloat16(v - __bfloat162float(h));
    }
    rr[tid]       += v0;
    rr[tid + 256] += v1;
    rr[tid + 512] += v2;
}

__global__ void __launch_bounds__(256)
final_ln_kernel(const float* __restrict__ x, const float* __restrict__ res,
                const float* __restrict__ w, const float* __restrict__ b,
                float* __restrict__ out) {
    int row = blockIdx.x;
    const float* xr = x + (size_t)row * DD;
    const float* rr = res + (size_t)row * DD;
    float* o = out + (size_t)row * DD;
    int tid = threadIdx.x;
    int lane = tid & 31, wid = tid >> 5;
    __shared__ float red[8];

    float v0 = xr[tid] + rr[tid];
    float v1 = xr[tid + 256] + rr[tid + 256];
    float v2 = xr[tid + 512] + rr[tid + 512];
    float mu = block_sum_256(v0 + v1 + v2, red, lane, wid) * (1.f / DD);
    __syncthreads();
    float d0 = v0 - mu, d1 = v1 - mu, d2 = v2 - mu;
    float var = block_sum_256(d0 * d0 + d1 * d1 + d2 * d2, red, lane, wid)
                * (1.f / DD);
    float inv = rsqrtf(var + 1e-5f);
    o[tid]       = d0 * inv * w[tid]       + b[tid];
    o[tid + 256] = d1 * inv * w[tid + 256] + b[tid + 256];
    o[tid + 512] = d2 * inv * w[tid + 512] + b[tid + 512];
}

// ===========================================================================
// Tensor-core GEMM (bf16 hi/lo, 3-pass): C[M,N] = A[M,K] * W[N,K]^T, fp32 C.
// R4 configuration: CTA 128x128, BK=32, 256 threads (8 warps: 2M x 4N),
// warp tile 64x32, 3-stage cp.async, XOR-swizzled 64B-pitch smem.
// ===========================================================================
__device__ __forceinline__ unsigned smem_u32(const void* p) {
    return (unsigned)__cvta_generic_to_shared(p);
}
__device__ __forceinline__ unsigned swz(int r, int c) {
    return (unsigned)(r * 64) + ((((unsigned)c >> 3) ^ (((unsigned)r >> 1) & 3u)) << 4);
}
__device__ __forceinline__ void ldsm_x4(unsigned* r, unsigned addr) {
    asm volatile("ldmatrix.sync.aligned.m8n8.x4.shared.b16 {%0,%1,%2,%3}, [%4];"
                 : "=r"(r[0]), "=r"(r[1]), "=r"(r[2]), "=r"(r[3]) : "r"(addr));
}
__device__ __forceinline__ void mma_bf16(float* c, const unsigned* a, const unsigned* b) {
    asm volatile(
        "mma.sync.aligned.m16n8k16.row.col.f32.bf16.bf16.f32 "
        "{%0,%1,%2,%3}, {%4,%5,%6,%7}, {%8,%9}, {%0,%1,%2,%3};"
        : "+f"(c[0]), "+f"(c[1]), "+f"(c[2]), "+f"(c[3])
        : "r"(a[0]), "r"(a[1]), "r"(a[2]), "r"(a[3]), "r"(b[0]), "r"(b[1]));
}
__device__ __forceinline__ void cp16(unsigned dst, const void* src) {
    asm volatile("cp.async.cg.shared.global [%0], [%1], 16;" :: "r"(dst), "l"(src));
}

constexpr int STAGE_BYTES = 32768;          // 4 arrays x 8KB
constexpr int NSTAGE = 3;
constexpr int ARR_A_H = 0, ARR_A_L = 8192, ARR_W_H = 16384, ARR_W_L = 24576;

__global__ void __launch_bounds__(256)
gemm_tc2_kernel(const __nv_bfloat16* __restrict__ Ahg,
                const __nv_bfloat16* __restrict__ Alg,
                const __nv_bfloat16* __restrict__ Whg,
                const __nv_bfloat16* __restrict__ Wlg,
                float* __restrict__ C, int ldc, int K) {
    extern __shared__ __align__(16) unsigned char smraw[];
    const unsigned sbase = smem_u32(smraw);

    const int tid  = threadIdx.x;
    const int lane = tid & 31;
    const int warp = tid >> 5;
    const int wm = (warp & 1) * 64;
    const int wn = (warp >> 1) * 32;
    const int m0 = blockIdx.y * 128;
    const int n0 = blockIdx.x * 128;

    const int lrow = tid >> 1;
    const int lq0  = (tid & 1) * 2;
    const size_t aoff = (size_t)(m0 + lrow) * K;
    const size_t woff = (size_t)(n0 + lrow) * K;
    const unsigned sdst0 = (unsigned)(lrow * 64) +
                           (((unsigned)lq0 ^ (((unsigned)lrow >> 1) & 3u)) << 4);
    const unsigned sdst1 = (unsigned)(lrow * 64) +
                           ((((unsigned)lq0 + 1u) ^ (((unsigned)lrow >> 1) & 3u)) << 4);

    const int nsteps = K / 32;

    auto load_stage = [&](int buf, int k0) {
        unsigned sb = sbase + buf * STAGE_BYTES;
        const __nv_bfloat16* pa_h = Ahg + aoff + k0 + lq0 * 8;
        const __nv_bfloat16* pa_l = Alg + aoff + k0 + lq0 * 8;
        const __nv_bfloat16* pw_h = Whg + woff + k0 + lq0 * 8;
        const __nv_bfloat16* pw_l = Wlg + woff + k0 + lq0 * 8;
        cp16(sb + ARR_A_H + sdst0, pa_h);
        cp16(sb + ARR_A_H + sdst1, pa_h + 8);
        cp16(sb + ARR_A_L + sdst0, pa_l);
        cp16(sb + ARR_A_L + sdst1, pa_l + 8);
        cp16(sb + ARR_W_H + sdst0, pw_h);
        cp16(sb + ARR_W_H + sdst1, pw_h + 8);
        cp16(sb + ARR_W_L + sdst0, pw_l);
        cp16(sb + ARR_W_L + sdst1, pw_l + 8);
    };

    float acc[4][4][4];
#pragma unroll
    for (int i = 0; i < 4; i++)
#pragma unroll
        for (int j = 0; j < 4; j++)
#pragma unroll
            for (int q = 0; q < 4; q++) acc[i][j][q] = 0.f;

    load_stage(0, 0);
    asm volatile("cp.async.commit_group;");
    load_stage(1, 32);
    asm volatile("cp.async.commit_group;");

    const int arow = wm + (lane & 7) + (lane & 8);
    const int brow = wn + (lane & 7) + ((lane >> 4) << 3);

    for (int s = 0; s < nsteps; s++) {
        asm volatile("cp.async.wait_group 1;");
        __syncthreads();
        if (s + 2 < nsteps) load_stage((s + 2) % NSTAGE, (s + 2) * 32);
        asm volatile("cp.async.commit_group;");

        const unsigned sb = sbase + (s % NSTAGE) * STAGE_BYTES;
#pragma unroll
        for (int kk = 0; kk < 32; kk += 16) {
            const int acol = kk + ((lane >> 4) << 3);
            const int bcol = kk + (lane & 8);
            unsigned af[4][4];
            unsigned whf[4][2], wlf[4][2];
#pragma unroll
            for (int mi = 0; mi < 4; mi++)
                ldsm_x4(af[mi], sb + ARR_A_H + swz(arow + mi * 16, acol));
#pragma unroll
            for (int nj = 0; nj < 2; nj++) {
                unsigned r[4];
                ldsm_x4(r, sb + ARR_W_H + swz(brow + nj * 16, bcol));
                whf[nj * 2][0] = r[0]; whf[nj * 2][1] = r[1];
                whf[nj * 2 + 1][0] = r[2]; whf[nj * 2 + 1][1] = r[3];
                ldsm_x4(r, sb + ARR_W_L + swz(brow + nj * 16, bcol));
                wlf[nj * 2][0] = r[0]; wlf[nj * 2][1] = r[1];
                wlf[nj * 2 + 1][0] = r[2]; wlf[nj * 2 + 1][1] = r[3];
            }
#pragma unroll
            for (int mi = 0; mi < 4; mi++)
#pragma unroll
                for (int ni = 0; ni < 4; ni++) {
                    mma_bf16(acc[mi][ni], af[mi], whf[ni]);
                    mma_bf16(acc[mi][ni], af[mi], wlf[ni]);
                }
#pragma unroll
            for (int mi = 0; mi < 4; mi++)
                ldsm_x4(af[mi], sb + ARR_A_L + swz(arow + mi * 16, acol));
#pragma unroll
            for (int mi = 0; mi < 4; mi++)
#pragma unroll
                for (int ni = 0; ni < 4; ni++)
                    mma_bf16(acc[mi][ni], af[mi], whf[ni]);
        }
    }

#pragma unroll
    for (int mi = 0; mi < 4; mi++) {
        int r0 = m0 + wm + mi * 16 + (lane >> 2);
#pragma unroll
        for (int ni = 0; ni < 4; ni++) {
            int c = n0 + wn + ni * 8 + (lane & 3) * 2;
            *(float2*)&C[(size_t)r0 * ldc + c] =
                make_float2(acc[mi][ni][0], acc[mi][ni][1]);
            *(float2*)&C[(size_t)(r0 + 8) * ldc + c] =
                make_float2(acc[mi][ni][2], acc[mi][ni][3]);
        }
    }
}

// ---------------------------------------------------------------------------
// x_proj split-K SIMT GEMM: part[kc] = xc[:, kc*384:(kc+1)*384] @ Wx^T slice
// grid (5, 32, XK), 256 threads. Then fixed-order reduce.
// ---------------------------------------------------------------------------
__global__ void __launch_bounds__(256)
gemm_xproj_kernel(const float* __restrict__ A, const float* __restrict__ W) {
    __shared__ float As[16][68];
    __shared__ float Ws[16][17];
    const int tid = threadIdx.x;
    const int tx = tid & 15, ty = tid >> 4;
    const int m0 = blockIdx.y * 64, n0 = blockIdx.x * 16;
    const int kc = blockIdx.z;
    const int kbase = kc * XKS;
    const int lrow = tid >> 2;
    const int lq = (tid & 3) * 4;

    float acc[4] = {0.f, 0.f, 0.f, 0.f};

    for (int k0 = 0; k0 < XKS; k0 += 16) {
        float4 av = *(const float4*)(A + (size_t)(m0 + lrow) * DIN + kbase + k0 + lq);
        As[lq + 0][lrow] = av.x; As[lq + 1][lrow] = av.y;
        As[lq + 2][lrow] = av.z; As[lq + 3][lrow] = av.w;
        if (tid < 64) {
            int wr = tid >> 2, wq = (tid & 3) * 4;
            float4 wv = *(const float4*)(W + (size_t)(n0 + wr) * DIN + kbase + k0 + wq);
            Ws[wq + 0][wr] = wv.x; Ws[wq + 1][wr] = wv.y;
            Ws[wq + 2][wr] = wv.z; Ws[wq + 3][wr] = wv.w;
        }
        __syncthreads();
#pragma unroll
        for (int kk = 0; kk < 16; kk++) {
            float4 a = *(const float4*)(&As[kk][ty * 4]);
            float wv = Ws[kk][tx];
            acc[0] += a.x * wv; acc[1] += a.y * wv;
            acc[2] += a.z * wv; acc[3] += a.w * wv;
        }
        __syncthreads();
    }
#pragma unroll
    for (int i = 0; i < 4; i++)
        g_dbc_part[kc][(size_t)(m0 + ty * 4 + i) * NR + n0 + tx] = acc[i];
}

__global__ void __launch_bounds__(256)
xproj_reduce_kernel(float* __restrict__ C) {
    int i = blockIdx.x * 256 + threadIdx.x;
    if (i >= TT * NR) return;
    float s = ((g_dbc_part[0][i] + g_dbc_part[1][i]) +
               (g_dbc_part[2][i] + g_dbc_part[3][i]));
    C[i] = s;
}

// ---------------------------------------------------------------------------
// dt GEMM (SIMT, K=48): dt = softplus(dbc[:,:48] @ Wdt^T + bdt)
// ---------------------------------------------------------------------------
__global__ void __launch_bounds__(256)
gemm_dt_kernel(const float* __restrict__ A, int lda,
               const float* __restrict__ W,
               const float* __restrict__ bias,
               float* __restrict__ C, int ldc, int N, int K) {
    __shared__ float As[16][132];
    __shared__ float Ws[16][68];
    const int tid = threadIdx.x;
    const int tx = tid & 15, ty = tid >> 4;
    const int m0 = blockIdx.y * 128, n0 = blockIdx.x * 64;
    const int ar = tid >> 1;
    const int ak = (tid & 1) * 8;
    const int wr = tid >> 2;
    const int wk = (tid & 3) * 4;

    float acc[8][4];
#pragma unroll
    for (int i = 0; i < 8; i++)
#pragma unroll
        for (int j = 0; j < 4; j++) acc[i][j] = 0.f;

    for (int k0 = 0; k0 < K; k0 += 16) {
        const float* ap = A + (size_t)(m0 + ar) * lda + k0 + ak;
        float4 a0 = *(const float4*)(ap);
        float4 a1 = *(const float4*)(ap + 4);
        As[ak + 0][ar] = a0.x; As[ak + 1][ar] = a0.y;
        As[ak + 2][ar] = a0.z; As[ak + 3][ar] = a0.w;
        As[ak + 4][ar] = a1.x; As[ak + 5][ar] = a1.y;
        As[ak + 6][ar] = a1.z; As[ak + 7][ar] = a1.w;
        float4 wv = *(const float4*)(W + (size_t)(n0 + wr) * K + k0 + wk);
        Ws[wk + 0][wr] = wv.x; Ws[wk + 1][wr] = wv.y;
        Ws[wk + 2][wr] = wv.z; Ws[wk + 3][wr] = wv.w;
        __syncthreads();
#pragma unroll
        for (int kk = 0; kk < 16; kk++) {
            float4 av0 = *(const float4*)(&As[kk][ty * 8]);
            float4 av1 = *(const float4*)(&As[kk][ty * 8 + 4]);
            float4 wv0 = *(const float4*)(&Ws[kk][tx * 4]);
            float a[8] = {av0.x, av0.y, av0.z, av0.w, av1.x, av1.y, av1.z, av1.w};
            float w[4] = {wv0.x, wv0.y, wv0.z, wv0.w};
#pragma unroll
            for (int i = 0; i < 8; i++)
#pragma unroll
                for (int j = 0; j < 4; j++)
                    acc[i][j] += a[i] * w[j];
        }
        __syncthreads();
    }
#pragma unroll
    for (int i = 0; i < 8; i++) {
        int m = m0 + ty * 8 + i;
#pragma unroll
        for (int j = 0; j < 4; j++) {
            int n = n0 + tx * 4 + j;
            float v = acc[i][j] + bias[n];
            v = (v > 20.f) ? v : log1pf(__expf(v));
            C[(size_t)m * ldc + n] = v;
        }
    }
}

// ---------------------------------------------------------------------------
// Causal depthwise conv (KC=4, left pad 3) + bias + SiLU, float4 over channels.
// ---------------------------------------------------------------------------
__global__ void __launch_bounds__(256)
conv_kernel(const float* __restrict__ xz, float* __restrict__ xc,
            const float* __restrict__ cw, const float* __restrict__ cb) {
    int idx = blockIdx.x * blockDim.x + threadIdx.x;
    if (idx >= TT * DIN / 4) return;
    int c4 = (idx % (DIN / 4)) * 4;
    int tb = idx / (DIN / 4);
    int t = tb % LL;
    int b = tb / LL;
    float4 acc = *(const float4*)(cb + c4);
    float4 w0 = *(const float4*)(cw + (c4 + 0) * KCC);
    float4 w1 = *(const float4*)(cw + (c4 + 1) * KCC);
    float4 w2 = *(const float4*)(cw + (c4 + 2) * KCC);
    float4 w3 = *(const float4*)(cw + (c4 + 3) * KCC);
    const float wk0[4] = {w0.x, w0.y, w0.z, w0.w};
    const float wk1[4] = {w1.x, w1.y, w1.z, w1.w};
    const float wk2[4] = {w2.x, w2.y, w2.z, w2.w};
    const float wk3[4] = {w3.x, w3.y, w3.z, w3.w};
#pragma unroll
    for (int k = 0; k < KCC; k++) {
        int tt = t - (KCC - 1) + k;
        if (tt >= 0) {
            float4 xv = *(const float4*)(
                xz + ((size_t)(b * LL + tt)) * (2 * DIN) + c4);
            acc.x += wk0[k] * xv.x;
            acc.y += wk1[k] * xv.y;
            acc.z += wk2[k] * xv.z;
            acc.w += wk3[k] * xv.w;
        }
    }
    acc.x = acc.x / (1.f + __expf(-acc.x));
    acc.y = acc.y / (1.f + __expf(-acc.y));
    acc.z = acc.z / (1.f + __expf(-acc.z));
    acc.w = acc.w / (1.f + __expf(-acc.w));
    *(float4*)(xc + (size_t)tb * DIN + c4) = acc;
}

// ===========================================================================
// Chunked selective scan (3 phases), CH=16, CS=64.
// ===========================================================================
__global__ void __launch_bounds__(256)
scan_p1_kernel(const float* __restrict__ dt, const float* __restrict__ xc,
               const float* __restrict__ dbc, const float* __restrict__ Alog) {
    int warp = threadIdx.x >> 5;
    int lane = threadIdx.x & 31;
    int n = lane & 15;
    int dl = lane >> 4;
    constexpr int BLOCKS_PER_B = DIN / 16;
    int b = blockIdx.x / BLOCKS_PER_B;
    int d = (blockIdx.x % BLOCKS_PER_B) * 16 + warp * 2 + dl;
    int c = blockIdx.y;

    float Av = -__expf(Alog[d * NSS + n]);
    float h = 0.f, sdt = 0.f;
    size_t rowbase = (size_t)b * LL + (size_t)c * CS;

    for (int t = 0; t < CS; t++) {
        size_t row = rowbase + t;
        float dtv = dt[row * DIN + d];
        float xv  = xc[row * DIN + d];
        float Bv  = dbc[row * NR + DRR + n];
        sdt += dtv;
        h = __expf(dtv * Av) * h + (dtv * xv) * Bv;
    }
    int idx = (b * DIN + d) * NSS + n;
    g_hend[(size_t)c * NSTATE + idx] = h;
    g_P[(size_t)c * NSTATE + idx]   = __expf(Av * sdt);
}

__global__ void __launch_bounds__(256)
scan_chain_kernel() {
    int i = blockIdx.x * 256 + threadIdx.x;
    if (i >= NSTATE) return;
    float hin = 0.f;
#pragma unroll
    for (int c = 0; c < CH; c++) {
        g_hinit[(size_t)c * NSTATE + i] = hin;
        hin = g_P[(size_t)c * NSTATE + i] * hin + g_hend[(size_t)c * NSTATE + i];
    }
}

__global__ void __launch_bounds__(256)
scan_p2_kernel(const float* __restrict__ dt, const float* __restrict__ xc,
               const float* __restrict__ dbc, const float* __restrict__ xz,
               __nv_bfloat16* __restrict__ yh, __nv_bfloat16* __restrict__ yl,
               const float* __restrict__ Alog, const float* __restrict__ Dp) {
    int warp = threadIdx.x >> 5;
    int lane = threadIdx.x & 31;
    int n = lane & 15;
    int dl = lane >> 4;
    constexpr int BLOCKS_PER_B = DIN / 16;
    int b = blockIdx.x / BLOCKS_PER_B;
    int d = (blockIdx.x % BLOCKS_PER_B) * 16 + warp * 2 + dl;
    int c = blockIdx.y;

    float Av = -__expf(Alog[d * NSS + n]);
    float Dv = Dp[d];
    int idx = (b * DIN + d) * NSS + n;
    float h = g_hinit[(size_t)c * NSTATE + idx];
    size_t rowbase = (size_t)b * LL + (size_t)c * CS;

    for (int t = 0; t < CS; t++) {
        size_t row = rowbase + t;
        float dtv = dt[row * DIN + d];
        float xv  = xc[row * DIN + d];
        float Bv  = dbc[row * NR + DRR + n];
        float Cv  = dbc[row * NR + DRR + NSS + n];
        h = __expf(dtv * Av) * h + (dtv * xv) * Bv;
        float yp = h * Cv;
        yp += __shfl_xor_sync(0xffffffffu, yp, 8);
        yp += __shfl_xor_sync(0xffffffffu, yp, 4);
        yp += __shfl_xor_sync(0xffffffffu, yp, 2);
        yp += __shfl_xor_sync(0xffffffffu, yp, 1);
        if (n == 0) {
            float zv = xz[row * (2 * DIN) + DIN + d];
            float sg = zv / (1.f + __expf(-zv));
            float g = (yp + xv * Dv) * sg;
            __nv_bfloat16 gh = __float2bfloat16(g);
            yh[row * DIN + d] = gh;
            yl[row * DIN + d] = __float2bfloat16(g - __bfloat162float(gh));
        }
    }
}

// ---------------------------------------------------------------------------
// Orchestration
// ---------------------------------------------------------------------------
extern "C" void kernel_launch(void* const* d_in, const int* in_sizes, int n_in,
                              void* d_out, int out_size) {
    const float* x        = (const float*)d_in[0];
    const float* ln_w     = (const float*)d_in[1];
    const float* ln_b     = (const float*)d_in[2];
    const float* in_proj  = (const float*)d_in[3];
    const float* conv_w   = (const float*)d_in[4];
    const float* conv_b   = (const float*)d_in[5];
    const float* x_proj   = (const float*)d_in[6];
    const float* dt_w     = (const float*)d_in[7];
    const float* dt_b     = (const float*)d_in[8];
    const float* A_log    = (const float*)d_in[9];
    const float* D_skip   = (const float*)d_in[10];
    const float* out_proj = (const float*)d_in[11];
    const float* fn_w     = (const float*)d_in[12];
    const float* fn_b     = (const float*)d_in[13];
    float* out = (float*)d_out;

    float* base = nullptr;
    cudaGetSymbolAddress((void**)&base, g_buf);
    float* bx   = base + O_X;
    float* bres = base + O_RES;
    float* bxz  = base + O_XZ;
    float* bxc  = base + O_XC;
    float* bdbc = base + O_DBC;
    float* bdt  = base + O_DT;

    __nv_bfloat16 *xnh, *xnl, *yh, *yl, *wih, *wil, *woh, *wol;
    cudaGetSymbolAddress((void**)&xnh, g_xn_h);
    cudaGetSymbolAddress((void**)&xnl, g_xn_l);
    cudaGetSymbolAddress((void**)&yh,  g_y_h);
    cudaGetSymbolAddress((void**)&yl,  g_y_l);
    cudaGetSymbolAddress((void**)&wih, g_wi_h);
    cudaGetSymbolAddress((void**)&wil, g_wi_l);
    cudaGetSymbolAddress((void**)&woh, g_wo_h);
    cudaGetSymbolAddress((void**)&wol, g_wo_l);

    cudaFuncSetAttribute(gemm_tc2_kernel,
                         cudaFuncAttributeMaxDynamicSharedMemorySize,
                         NSTAGE * STAGE_BYTES);

    cvt_weights_kernel<<<(unsigned)((NWI + NWO + 255) / 256), 256>>>(in_proj, out_proj);
    init_kernel<<<(TT * DD) / 256, 256>>>(x, bx, bres);

    for (int l = 0; l < NLAY; l++) {
        layer_ln_kernel<<<TT, 256>>>(bx, bres, xnh, xnl,
                                     ln_w + (size_t)l * DD, ln_b + (size_t)l * DD);
        // xz = xn @ Wi^T   (2048 x 3072, K=768)
        gemm_tc2_kernel<<<dim3((2 * DIN) / 128, TT / 128), 256,
                          NSTAGE * STAGE_BYTES>>>(
            xnh, xnl,
            wih + (size_t)l * 2 * DIN * DD, wil + (size_t)l * 2 * DIN * DD,
            bxz, 2 * DIN, DD);
        // xc = silu(conv(xi) + cb)
        conv_kernel<<<(TT * DIN / 4) / 256, 256>>>(
            bxz, bxc, conv_w + (size_t)l * DIN * KCC, conv_b + (size_t)l * DIN);
        // dbc = xc @ Wx^T  (split-K x4 + reduce)
        gemm_xproj_kernel<<<dim3(NR / 16, TT / 64, XK), 256>>>(
            bxc, x_proj + (size_t)l * NR * DIN);
        xproj_reduce_kernel<<<(TT * NR + 255) / 256, 256>>>(bdbc);
        // dt = softplus(dbc[:, :48] @ Wdt^T + bdt)
        gemm_dt_kernel<<<dim3(DIN / 64, TT / 128), 256>>>(
            bdbc, NR, dt_w + (size_t)l * DIN * DRR, dt_b + (size_t)l * DIN,
            bdt, DIN, DIN, DRR);
        // chunked selective scan
        scan_p1_kernel<<<dim3(BB * (DIN / 16), CH), 256>>>(
            bdt, bxc, bdbc, A_log + (size_t)l * DIN * NSS);
        scan_chain_kernel<<<(NSTATE + 255) / 256, 256>>>();
        scan_p2_kernel<<<dim3(BB * (DIN / 16), CH), 256>>>(
            bdt, bxc, bdbc, bxz, yh, yl,
            A_log + (size_t)l * DIN * NSS, D_skip + (size_t)l * DIN);
        // x_next = y @ Wo^T  (2048 x 768, K=1536)
        gemm_tc2_kernel<<<dim3(DD / 128, TT / 128), 256,
                          NSTAGE * STAGE_BYTES>>>(
            yh, yl,
            woh + (size_t)l * DD * DIN, wol + (size_t)l * DD * DIN,
            bx, DD, DIN);
    }

    final_ln_kernel<<<TT, 256>>>(bx, bres, fn_w, fn_b, out);
}

// round 8
// speedup vs baseline: 1.9829x; 1.0278x over previous
#include <cuda_runtime.h>
#include <cuda_bf16.h>
#include <math.h>
#include <stdint.h>

// Problem constants
constexpr int BB   = 2;
constexpr int LL   = 1024;
constexpr int DD   = 768;
constexpr int NLAY = 8;
constexpr int DIN  = 1536;       // 2*D
constexpr int NSS  = 16;
constexpr int DRR  = 48;         // D/16
constexpr int KCC  = 4;
constexpr int TT   = BB * LL;    // 2048 tokens
constexpr int NR   = DRR + 2 * NSS;  // 80

// Chunked scan
constexpr int CH = 16;
constexpr int CS = LL / CH;      // 64
constexpr int NSTATE = BB * DIN * NSS;   // 49152

// x_proj split-K
constexpr int XK = 4;
constexpr int XKS = DIN / XK;    // 384

// out_proj split-K
constexpr int OK = 3;
constexpr int OKS = DIN / OK;    // 512

// fp32 scratch
constexpr size_t O_RES = 0;
constexpr size_t O_XZ  = O_RES + (size_t)TT * DD;
constexpr size_t O_XC  = O_XZ  + (size_t)TT * 2 * DIN;
constexpr size_t O_DBC = O_XC  + (size_t)TT * DIN;
constexpr size_t O_DT  = O_DBC + (size_t)TT * NR;
constexpr size_t O_END = O_DT  + (size_t)TT * DIN;
__device__ float g_buf[O_END];

__device__ float g_hend[(size_t)CH * NSTATE];
__device__ float g_P[(size_t)CH * NSTATE];
__device__ float g_hinit[(size_t)CH * NSTATE];
__device__ float g_dbc_part[XK][(size_t)TT * NR];
__device__ float g_xf_part[OK][(size_t)TT * DD];

// bf16 hi/lo activation + weight buffers
constexpr size_t NWI = (size_t)NLAY * 2 * DIN * DD;
constexpr size_t NWO = (size_t)NLAY * DD * DIN;
__device__ __nv_bfloat16 g_xn_h[(size_t)TT * DD];
__device__ __nv_bfloat16 g_xn_l[(size_t)TT * DD];
__device__ __nv_bfloat16 g_y_h[(size_t)TT * DIN];
__device__ __nv_bfloat16 g_y_l[(size_t)TT * DIN];
__device__ __nv_bfloat16 g_wi_h[NWI];
__device__ __nv_bfloat16 g_wi_l[NWI];
__device__ __nv_bfloat16 g_wo_h[NWO];
__device__ __nv_bfloat16 g_wo_l[NWO];

// ---------------------------------------------------------------------------
// weight conversion: fp32 -> bf16 hi/lo (once per launch)
// ---------------------------------------------------------------------------
__global__ void cvt_weights_kernel(const float* __restrict__ wi,
                                   const float* __restrict__ wo) {
    size_t i = (size_t)blockIdx.x * 256 + threadIdx.x;
    if (i < NWI) {
        float v = wi[i];
        __nv_bfloat16 h = __float2bfloat16(v);
        g_wi_h[i] = h;
        g_wi_l[i] = __float2bfloat16(v - __bfloat162float(h));
    } else if (i < NWI + NWO) {
        size_t j = i - NWI;
        float v = wo[j];
        __nv_bfloat16 h = __float2bfloat16(v);
        g_wo_h[j] = h;
        g_wo_l[j] = __float2bfloat16(v - __bfloat162float(h));
    }
}

// ---------------------------------------------------------------------------
// Warp-shuffle block reduction helper (256 threads / 8 warps)
// ---------------------------------------------------------------------------
__device__ __forceinline__ float block_sum_256(float v, float* red,
                                               int lane, int wid) {
#pragma unroll
    for (int o = 16; o > 0; o >>= 1)
        v += __shfl_xor_sync(0xffffffffu, v, o);
    if (lane == 0) red[wid] = v;
    __syncthreads();
    return red[0] + red[1] + red[2] + red[3] +
           red[4] + red[5] + red[6] + red[7];
}

__device__ __forceinline__ void ln_emit(float d0, float d1, float d2, float inv,
                                        int tid, size_t rowoff,
                                        const float* __restrict__ w,
                                        const float* __restrict__ b,
                                        __nv_bfloat16* __restrict__ xnh,
                                        __nv_bfloat16* __restrict__ xnl) {
#pragma unroll
    for (int c = 0; c < 3; c++) {
        int i = tid + c * 256;
        float dv = (c == 0 ? d0 : c == 1 ? d1 : d2);
        float v = dv * inv * w[i] + b[i];
        __nv_bfloat16 h = __float2bfloat16(v);
        xnh[rowoff + i] = h;
        xnl[rowoff + i] = __float2bfloat16(v - __bfloat162float(h));
    }
}

// ---------------------------------------------------------------------------
// Layer-0 LN: reads input x; res = x; xn = LN(x) -> bf16 hi/lo
// ---------------------------------------------------------------------------
__global__ void __launch_bounds__(256)
ln_first_kernel(const float* __restrict__ x, float* __restrict__ res,
                __nv_bfloat16* __restrict__ xnh, __nv_bfloat16* __restrict__ xnl,
                const float* __restrict__ w, const float* __restrict__ b) {
    int row = blockIdx.x;
    size_t ro = (size_t)row * DD;
    int tid = threadIdx.x;
    int lane = tid & 31, wid = tid >> 5;
    __shared__ float red[8];

    float v0 = x[ro + tid], v1 = x[ro + tid + 256], v2 = x[ro + tid + 512];
    float mu = block_sum_256(v0 + v1 + v2, red, lane, wid) * (1.f / DD);
    __syncthreads();
    float d0 = v0 - mu, d1 = v1 - mu, d2 = v2 - mu;
    float var = block_sum_256(d0 * d0 + d1 * d1 + d2 * d2, red, lane, wid)
                * (1.f / DD);
    float inv = rsqrtf(var + 1e-5f);
    ln_emit(d0, d1, d2, inv, tid, ro, w, b, xnh, xnl);
    res[ro + tid]       = v0;
    res[ro + tid + 256] = v1;
    res[ro + tid + 512] = v2;
}

// ---------------------------------------------------------------------------
// Fused out_proj reduce + next-layer LN: v = sum of OK partials;
// res += v; xn = LN(v)*w + b
// ---------------------------------------------------------------------------
__global__ void __launch_bounds__(256)
ln_fuse_kernel(float* __restrict__ res,
               __nv_bfloat16* __restrict__ xnh, __nv_bfloat16* __restrict__ xnl,
               const float* __restrict__ w, const float* __restrict__ b) {
    int row = blockIdx.x;
    size_t ro = (size_t)row * DD;
    int tid = threadIdx.x;
    int lane = tid & 31, wid = tid >> 5;
    __shared__ float red[8];

    float v0 = g_xf_part[0][ro + tid] + g_xf_part[1][ro + tid] +
               g_xf_part[2][ro + tid];
    float v1 = g_xf_part[0][ro + tid + 256] + g_xf_part[1][ro + tid + 256] +
               g_xf_part[2][ro + tid + 256];
    float v2 = g_xf_part[0][ro + tid + 512] + g_xf_part[1][ro + tid + 512] +
               g_xf_part[2][ro + tid + 512];
    float mu = block_sum_256(v0 + v1 + v2, red, lane, wid) * (1.f / DD);
    __syncthreads();
    float d0 = v0 - mu, d1 = v1 - mu, d2 = v2 - mu;
    float var = block_sum_256(d0 * d0 + d1 * d1 + d2 * d2, red, lane, wid)
                * (1.f / DD);
    float inv = rsqrtf(var + 1e-5f);
    ln_emit(d0, d1, d2, inv, tid, ro, w, b, xnh, xnl);
    res[ro + tid]       += v0;
    res[ro + tid + 256] += v1;
    res[ro + tid + 512] += v2;
}

// ---------------------------------------------------------------------------
// Final fused: v = sum partials + res; out = LN(v)*fw + fb
// ---------------------------------------------------------------------------
__global__ void __launch_bounds__(256)
final_fuse_kernel(const float* __restrict__ res,
                  const float* __restrict__ w, const float* __restrict__ b,
                  float* __restrict__ out) {
    int row = blockIdx.x;
    size_t ro = (size_t)row * DD;
    int tid = threadIdx.x;
    int lane = tid & 31, wid = tid >> 5;
    __shared__ float red[8];

    float v0 = g_xf_part[0][ro + tid] + g_xf_part[1][ro + tid] +
               g_xf_part[2][ro + tid] + res[ro + tid];
    float v1 = g_xf_part[0][ro + tid + 256] + g_xf_part[1][ro + tid + 256] +
               g_xf_part[2][ro + tid + 256] + res[ro + tid + 256];
    float v2 = g_xf_part[0][ro + tid + 512] + g_xf_part[1][ro + tid + 512] +
               g_xf_part[2][ro + tid + 512] + res[ro + tid + 512];
    float mu = block_sum_256(v0 + v1 + v2, red, lane, wid) * (1.f / DD);
    __syncthreads();
    float d0 = v0 - mu, d1 = v1 - mu, d2 = v2 - mu;
    float var = block_sum_256(d0 * d0 + d1 * d1 + d2 * d2, red, lane, wid)
                * (1.f / DD);
    float inv = rsqrtf(var + 1e-5f);
    out[ro + tid]       = d0 * inv * w[tid]       + b[tid];
    out[ro + tid + 256] = d1 * inv * w[tid + 256] + b[tid + 256];
    out[ro + tid + 512] = d2 * inv * w[tid + 512] + b[tid + 512];
}

// ===========================================================================
// Tensor-core GEMM (bf16 hi/lo, 3-pass), R4 shape, with optional split-K:
// CTA 128x128, BK=32, 256 thr (8 warps 2Mx4N, warp 64x32), 3-stage cp.async.
// blockIdx.z selects k-chunk; output goes to C + z*partStride.
// ===========================================================================
__device__ __forceinline__ unsigned smem_u32(const void* p) {
    return (unsigned)__cvta_generic_to_shared(p);
}
__device__ __forceinline__ unsigned swz(int r, int c) {
    return (unsigned)(r * 64) + ((((unsigned)c >> 3) ^ (((unsigned)r >> 1) & 3u)) << 4);
}
__device__ __forceinline__ void ldsm_x4(unsigned* r, unsigned addr) {
    asm volatile("ldmatrix.sync.aligned.m8n8.x4.shared.b16 {%0,%1,%2,%3}, [%4];"
                 : "=r"(r[0]), "=r"(r[1]), "=r"(r[2]), "=r"(r[3]) : "r"(addr));
}
__device__ __forceinline__ void mma_bf16(float* c, const unsigned* a, const unsigned* b) {
    asm volatile(
        "mma.sync.aligned.m16n8k16.row.col.f32.bf16.bf16.f32 "
        "{%0,%1,%2,%3}, {%4,%5,%6,%7}, {%8,%9}, {%0,%1,%2,%3};"
        : "+f"(c[0]), "+f"(c[1]), "+f"(c[2]), "+f"(c[3])
        : "r"(a[0]), "r"(a[1]), "r"(a[2]), "r"(a[3]), "r"(b[0]), "r"(b[1]));
}
__device__ __forceinline__ void cp16(unsigned dst, const void* src) {
    asm volatile("cp.async.cg.shared.global [%0], [%1], 16;" :: "r"(dst), "l"(src));
}

constexpr int STAGE_BYTES = 32768;
constexpr int NSTAGE = 3;
constexpr int ARR_A_H = 0, ARR_A_L = 8192, ARR_W_H = 16384, ARR_W_L = 24576;

__global__ void __launch_bounds__(256)
gemm_tc2_kernel(const __nv_bfloat16* __restrict__ Ahg,
                const __nv_bfloat16* __restrict__ Alg,
                const __nv_bfloat16* __restrict__ Whg,
                const __nv_bfloat16* __restrict__ Wlg,
                float* __restrict__ C, int ldc,
                int Ksplit, int Kfull, size_t partStride) {
    extern __shared__ __align__(16) unsigned char smraw[];
    const unsigned sbase = smem_u32(smraw);

    const int tid  = threadIdx.x;
    const int lane = tid & 31;
    const int warp = tid >> 5;
    const int wm = (warp & 1) * 64;
    const int wn = (warp >> 1) * 32;
    const int m0 = blockIdx.y * 128;
    const int n0 = blockIdx.x * 128;
    const int koff = blockIdx.z * Ksplit;
    float* Cout = C + (size_t)blockIdx.z * partStride;

    const int lrow = tid >> 1;
    const int lq0  = (tid & 1) * 2;
    const size_t aoff = (size_t)(m0 + lrow) * Kfull + koff;
    const size_t woff = (size_t)(n0 + lrow) * Kfull + koff;
    const unsigned sdst0 = (unsigned)(lrow * 64) +
                           (((unsigned)lq0 ^ (((unsigned)lrow >> 1) & 3u)) << 4);
    const unsigned sdst1 = (unsigned)(lrow * 64) +
                           ((((unsigned)lq0 + 1u) ^ (((unsigned)lrow >> 1) & 3u)) << 4);

    const int nsteps = Ksplit / 32;

    auto load_stage = [&](int buf, int k0) {
        unsigned sb = sbase + buf * STAGE_BYTES;
        const __nv_bfloat16* pa_h = Ahg + aoff + k0 + lq0 * 8;
        const __nv_bfloat16* pa_l = Alg + aoff + k0 + lq0 * 8;
        const __nv_bfloat16* pw_h = Whg + woff + k0 + lq0 * 8;
        const __nv_bfloat16* pw_l = Wlg + woff + k0 + lq0 * 8;
        cp16(sb + ARR_A_H + sdst0, pa_h);
        cp16(sb + ARR_A_H + sdst1, pa_h + 8);
        cp16(sb + ARR_A_L + sdst0, pa_l);
        cp16(sb + ARR_A_L + sdst1, pa_l + 8);
        cp16(sb + ARR_W_H + sdst0, pw_h);
        cp16(sb + ARR_W_H + sdst1, pw_h + 8);
        cp16(sb + ARR_W_L + sdst0, pw_l);
        cp16(sb + ARR_W_L + sdst1, pw_l + 8);
    };

    float acc[4][4][4];
#pragma unroll
    for (int i = 0; i < 4; i++)
#pragma unroll
        for (int j = 0; j < 4; j++)
#pragma unroll
            for (int q = 0; q < 4; q++) acc[i][j][q] = 0.f;

    load_stage(0, 0);
    asm volatile("cp.async.commit_group;");
    load_stage(1, 32);
    asm volatile("cp.async.commit_group;");

    const int arow = wm + (lane & 7) + (lane & 8);
    const int brow = wn + (lane & 7) + ((lane >> 4) << 3);

    for (int s = 0; s < nsteps; s++) {
        asm volatile("cp.async.wait_group 1;");
        __syncthreads();
        if (s + 2 < nsteps) load_stage((s + 2) % NSTAGE, (s + 2) * 32);
        asm volatile("cp.async.commit_group;");

        const unsigned sb = sbase + (s % NSTAGE) * STAGE_BYTES;
#pragma unroll
        for (int kk = 0; kk < 32; kk += 16) {
            const int acol = kk + ((lane >> 4) << 3);
            const int bcol = kk + (lane & 8);
            unsigned af[4][4];
            unsigned whf[4][2], wlf[4][2];
#pragma unroll
            for (int mi = 0; mi < 4; mi++)
                ldsm_x4(af[mi], sb + ARR_A_H + swz(arow + mi * 16, acol));
#pragma unroll
            for (int nj = 0; nj < 2; nj++) {
                unsigned r[4];
                ldsm_x4(r, sb + ARR_W_H + swz(brow + nj * 16, bcol));
                whf[nj * 2][0] = r[0]; whf[nj * 2][1] = r[1];
                whf[nj * 2 + 1][0] = r[2]; whf[nj * 2 + 1][1] = r[3];
                ldsm_x4(r, sb + ARR_W_L + swz(brow + nj * 16, bcol));
                wlf[nj * 2][0] = r[0]; wlf[nj * 2][1] = r[1];
                wlf[nj * 2 + 1][0] = r[2]; wlf[nj * 2 + 1][1] = r[3];
            }
#pragma unroll
            for (int mi = 0; mi < 4; mi++)
#pragma unroll
                for (int ni = 0; ni < 4; ni++) {
                    mma_bf16(acc[mi][ni], af[mi], whf[ni]);
                    mma_bf16(acc[mi][ni], af[mi], wlf[ni]);
                }
#pragma unroll
            for (int mi = 0; mi < 4; mi++)
                ldsm_x4(af[mi], sb + ARR_A_L + swz(arow + mi * 16, acol));
#pragma unroll
            for (int mi = 0; mi < 4; mi++)
#pragma unroll
                for (int ni = 0; ni < 4; ni++)
                    mma_bf16(acc[mi][ni], af[mi], whf[ni]);
        }
    }

#pragma unroll
    for (int mi = 0; mi < 4; mi++) {
        int r0 = m0 + wm + mi * 16 + (lane >> 2);
#pragma unroll
        for (int ni = 0; ni < 4; ni++) {
            int c = n0 + wn + ni * 8 + (lane & 3) * 2;
            *(float2*)&Cout[(size_t)r0 * ldc + c] =
                make_float2(acc[mi][ni][0], acc[mi][ni][1]);
            *(float2*)&Cout[(size_t)(r0 + 8) * ldc + c] =
                make_float2(acc[mi][ni][2], acc[mi][ni][3]);
        }
    }
}

// ---------------------------------------------------------------------------
// x_proj split-K SIMT GEMM + reduce
// ---------------------------------------------------------------------------
__global__ void __launch_bounds__(256)
gemm_xproj_kernel(const float* __restrict__ A, const float* __restrict__ W) {
    __shared__ float As[16][68];
    __shared__ float Ws[16][17];
    const int tid = threadIdx.x;
    const int tx = tid & 15, ty = tid >> 4;
    const int m0 = blockIdx.y * 64, n0 = blockIdx.x * 16;
    const int kc = blockIdx.z;
    const int kbase = kc * XKS;
    const int lrow = tid >> 2;
    const int lq = (tid & 3) * 4;

    float acc[4] = {0.f, 0.f, 0.f, 0.f};

    for (int k0 = 0; k0 < XKS; k0 += 16) {
        float4 av = *(const float4*)(A + (size_t)(m0 + lrow) * DIN + kbase + k0 + lq);
        As[lq + 0][lrow] = av.x; As[lq + 1][lrow] = av.y;
        As[lq + 2][lrow] = av.z; As[lq + 3][lrow] = av.w;
        if (tid < 64) {
            int wr = tid >> 2, wq = (tid & 3) * 4;
            float4 wv = *(const float4*)(W + (size_t)(n0 + wr) * DIN + kbase + k0 + wq);
            Ws[wq + 0][wr] = wv.x; Ws[wq + 1][wr] = wv.y;
            Ws[wq + 2][wr] = wv.z; Ws[wq + 3][wr] = wv.w;
        }
        __syncthreads();
#pragma unroll
        for (int kk = 0; kk < 16; kk++) {
            float4 a = *(const float4*)(&As[kk][ty * 4]);
            float wv = Ws[kk][tx];
            acc[0] += a.x * wv; acc[1] += a.y * wv;
            acc[2] += a.z * wv; acc[3] += a.w * wv;
        }
        __syncthreads();
    }
#pragma unroll
    for (int i = 0; i < 4; i++)
        g_dbc_part[kc][(size_t)(m0 + ty * 4 + i) * NR + n0 + tx] = acc[i];
}

__global__ void __launch_bounds__(256)
xproj_reduce_kernel(float* __restrict__ C) {
    int i = blockIdx.x * 256 + threadIdx.x;
    if (i >= TT * NR) return;
    C[i] = (g_dbc_part[0][i] + g_dbc_part[1][i]) +
           (g_dbc_part[2][i] + g_dbc_part[3][i]);
}

// ---------------------------------------------------------------------------
// dt GEMM (SIMT, K=48): dt = softplus(dbc[:,:48] @ Wdt^T + bdt)
// ---------------------------------------------------------------------------
__global__ void __launch_bounds__(256)
gemm_dt_kernel(const float* __restrict__ A, int lda,
               const float* __restrict__ W,
               const float* __restrict__ bias,
               float* __restrict__ C, int ldc, int N, int K) {
    __shared__ float As[16][132];
    __shared__ float Ws[16][68];
    const int tid = threadIdx.x;
    const int tx = tid & 15, ty = tid >> 4;
    const int m0 = blockIdx.y * 128, n0 = blockIdx.x * 64;
    const int ar = tid >> 1;
    const int ak = (tid & 1) * 8;
    const int wr = tid >> 2;
    const int wk = (tid & 3) * 4;

    float acc[8][4];
#pragma unroll
    for (int i = 0; i < 8; i++)
#pragma unroll
        for (int j = 0; j < 4; j++) acc[i][j] = 0.f;

    for (int k0 = 0; k0 < K; k0 += 16) {
        const float* ap = A + (size_t)(m0 + ar) * lda + k0 + ak;
        float4 a0 = *(const float4*)(ap);
        float4 a1 = *(const float4*)(ap + 4);
        As[ak + 0][ar] = a0.x; As[ak + 1][ar] = a0.y;
        As[ak + 2][ar] = a0.z; As[ak + 3][ar] = a0.w;
        As[ak + 4][ar] = a1.x; As[ak + 5][ar] = a1.y;
        As[ak + 6][ar] = a1.z; As[ak + 7][ar] = a1.w;
        float4 wv = *(const float4*)(W + (size_t)(n0 + wr) * K + k0 + wk);
        Ws[wk + 0][wr] = wv.x; Ws[wk + 1][wr] = wv.y;
        Ws[wk + 2][wr] = wv.z; Ws[wk + 3][wr] = wv.w;
        __syncthreads();
#pragma unroll
        for (int kk = 0; kk < 16; kk++) {
            float4 av0 = *(const float4*)(&As[kk][ty * 8]);
            float4 av1 = *(const float4*)(&As[kk][ty * 8 + 4]);
            float4 wv0 = *(const float4*)(&Ws[kk][tx * 4]);
            float a[8] = {av0.x, av0.y, av0.z, av0.w, av1.x, av1.y, av1.z, av1.w};
            float w[4] = {wv0.x, wv0.y, wv0.z, wv0.w};
#pragma unroll
            for (int i = 0; i < 8; i++)
#pragma unroll
                for (int j = 0; j < 4; j++)
                    acc[i][j] += a[i] * w[j];
        }
        __syncthreads();
    }
#pragma unroll
    for (int i = 0; i < 8; i++) {
        int m = m0 + ty * 8 + i;
#pragma unroll
        for (int j = 0; j < 4; j++) {
            int n = n0 + tx * 4 + j;
            float v = acc[i][j] + bias[n];
            v = (v > 20.f) ? v : log1pf(__expf(v));
            C[(size_t)m * ldc + n] = v;
        }
    }
}

// ---------------------------------------------------------------------------
// Causal depthwise conv (KC=4, left pad 3) + bias + SiLU, float4 over channels.
// ---------------------------------------------------------------------------
__global__ void __launch_bounds__(256)
conv_kernel(const float* __restrict__ xz, float* __restrict__ xc,
            const float* __restrict__ cw, const float* __restrict__ cb) {
    int idx = blockIdx.x * blockDim.x + threadIdx.x;
    if (idx >= TT * DIN / 4) return;
    int c4 = (idx % (DIN / 4)) * 4;
    int tb = idx / (DIN / 4);
    int t = tb % LL;
    int b = tb / LL;
    float4 acc = *(const float4*)(cb + c4);
    float4 w0 = *(const float4*)(cw + (c4 + 0) * KCC);
    float4 w1 = *(const float4*)(cw + (c4 + 1) * KCC);
    float4 w2 = *(const float4*)(cw + (c4 + 2) * KCC);
    float4 w3 = *(const float4*)(cw + (c4 + 3) * KCC);
    const float wk0[4] = {w0.x, w0.y, w0.z, w0.w};
    const float wk1[4] = {w1.x, w1.y, w1.z, w1.w};
    const float wk2[4] = {w2.x, w2.y, w2.z, w2.w};
    const float wk3[4] = {w3.x, w3.y, w3.z, w3.w};
#pragma unroll
    for (int k = 0; k < KCC; k++) {
        int tt = t - (KCC - 1) + k;
        if (tt >= 0) {
            float4 xv = *(const float4*)(
                xz + ((size_t)(b * LL + tt)) * (2 * DIN) + c4);
            acc.x += wk0[k] * xv.x;
            acc.y += wk1[k] * xv.y;
            acc.z += wk2[k] * xv.z;
            acc.w += wk3[k] * xv.w;
        }
    }
    acc.x = acc.x / (1.f + __expf(-acc.x));
    acc.y = acc.y / (1.f + __expf(-acc.y));
    acc.z = acc.z / (1.f + __expf(-acc.z));
    acc.w = acc.w / (1.f + __expf(-acc.w));
    *(float4*)(xc + (size_t)tb * DIN + c4) = acc;
}

// ===========================================================================
// Chunked selective scan (3 phases), CH=16, CS=64.
// ===========================================================================
__global__ void __launch_bounds__(256)
scan_p1_kernel(const float* __restrict__ dt, const float* __restrict__ xc,
               const float* __restrict__ dbc, const float* __restrict__ Alog) {
    int warp = threadIdx.x >> 5;
    int lane = threadIdx.x & 31;
    int n = lane & 15;
    int dl = lane >> 4;
    constexpr int BLOCKS_PER_B = DIN / 16;
    int b = blockIdx.x / BLOCKS_PER_B;
    int d = (blockIdx.x % BLOCKS_PER_B) * 16 + warp * 2 + dl;
    int c = blockIdx.y;

    float Av = -__expf(Alog[d * NSS + n]);
    float h = 0.f, sdt = 0.f;
    size_t rowbase = (size_t)b * LL + (size_t)c * CS;

    for (int t = 0; t < CS; t++) {
        size_t row = rowbase + t;
        float dtv = dt[row * DIN + d];
        float xv  = xc[row * DIN + d];
        float Bv  = dbc[row * NR + DRR + n];
        sdt += dtv;
        h = __expf(dtv * Av) * h + (dtv * xv) * Bv;
    }
    int idx = (b * DIN + d) * NSS + n;
    g_hend[(size_t)c * NSTATE + idx] = h;
    g_P[(size_t)c * NSTATE + idx]   = __expf(Av * sdt);
}

__global__ void __launch_bounds__(256)
scan_chain_kernel() {
    int i = blockIdx.x * 256 + threadIdx.x;
    if (i >= NSTATE) return;
    float hin = 0.f;
#pragma unroll
    for (int c = 0; c < CH; c++) {
        g_hinit[(size_t)c * NSTATE + i] = hin;
        hin = g_P[(size_t)c * NSTATE + i] * hin + g_hend[(size_t)c * NSTATE + i];
    }
}

__global__ void __launch_bounds__(256)
scan_p2_kernel(const float* __restrict__ dt, const float* __restrict__ xc,
               const float* __restrict__ dbc, const float* __restrict__ xz,
               __nv_bfloat16* __restrict__ yh, __nv_bfloat16* __restrict__ yl,
               const float* __restrict__ Alog, const float* __restrict__ Dp) {
    int warp = threadIdx.x >> 5;
    int lane = threadIdx.x & 31;
    int n = lane & 15;
    int dl = lane >> 4;
    constexpr int BLOCKS_PER_B = DIN / 16;
    int b = blockIdx.x / BLOCKS_PER_B;
    int d = (blockIdx.x % BLOCKS_PER_B) * 16 + warp * 2 + dl;
    int c = blockIdx.y;

    float Av = -__expf(Alog[d * NSS + n]);
    float Dv = Dp[d];
    int idx = (b * DIN + d) * NSS + n;
    float h = g_hinit[(size_t)c * NSTATE + idx];
    size_t rowbase = (size_t)b * LL + (size_t)c * CS;

    for (int t = 0; t < CS; t++) {
        size_t row = rowbase + t;
        float dtv = dt[row * DIN + d];
        float xv  = xc[row * DIN + d];
        float Bv  = dbc[row * NR + DRR + n];
        float Cv  = dbc[row * NR + DRR + NSS + n];
        h = __expf(dtv * Av) * h + (dtv * xv) * Bv;
        float yp = h * Cv;
        yp += __shfl_xor_sync(0xffffffffu, yp, 8);
        yp += __shfl_xor_sync(0xffffffffu, yp, 4);
        yp += __shfl_xor_sync(0xffffffffu, yp, 2);
        yp += __shfl_xor_sync(0xffffffffu, yp, 1);
        if (n == 0) {
            float zv = xz[row * (2 * DIN) + DIN + d];
            float sg = zv / (1.f + __expf(-zv));
            float g = (yp + xv * Dv) * sg;
            __nv_bfloat16 gh = __float2bfloat16(g);
            yh[row * DIN + d] = gh;
            yl[row * DIN + d] = __float2bfloat16(g - __bfloat162float(gh));
        }
    }
}

// ---------------------------------------------------------------------------
// Orchestration
// ---------------------------------------------------------------------------
extern "C" void kernel_launch(void* const* d_in, const int* in_sizes, int n_in,
                              void* d_out, int out_size) {
    const float* x        = (const float*)d_in[0];
    const float* ln_w     = (const float*)d_in[1];
    const float* ln_b     = (const float*)d_in[2];
    const float* in_proj  = (const float*)d_in[3];
    const float* conv_w   = (const float*)d_in[4];
    const float* conv_b   = (const float*)d_in[5];
    const float* x_proj   = (const float*)d_in[6];
    const float* dt_w     = (const float*)d_in[7];
    const float* dt_b     = (const float*)d_in[8];
    const float* A_log    = (const float*)d_in[9];
    const float* D_skip   = (const float*)d_in[10];
    const float* out_proj = (const float*)d_in[11];
    const float* fn_w     = (const float*)d_in[12];
    const float* fn_b     = (const float*)d_in[13];
    float* out = (float*)d_out;

    float* base = nullptr;
    cudaGetSymbolAddress((void**)&base, g_buf);
    float* bres = base + O_RES;
    float* bxz  = base + O_XZ;
    float* bxc  = base + O_XC;
    float* bdbc = base + O_DBC;
    float* bdt  = base + O_DT;

    __nv_bfloat16 *xnh, *xnl, *yh, *yl, *wih, *wil, *woh, *wol;
    cudaGetSymbolAddress((void**)&xnh, g_xn_h);
    cudaGetSymbolAddress((void**)&xnl, g_xn_l);
    cudaGetSymbolAddress((void**)&yh,  g_y_h);
    cudaGetSymbolAddress((void**)&yl,  g_y_l);
    cudaGetSymbolAddress((void**)&wih, g_wi_h);
    cudaGetSymbolAddress((void**)&wil, g_wi_l);
    cudaGetSymbolAddress((void**)&woh, g_wo_h);
    cudaGetSymbolAddress((void**)&wol, g_wo_l);

    float* xfpart = nullptr;
    cudaGetSymbolAddress((void**)&xfpart, g_xf_part);

    cudaFuncSetAttribute(gemm_tc2_kernel,
                         cudaFuncAttributeMaxDynamicSharedMemorySize,
                         NSTAGE * STAGE_BYTES);

    cvt_weights_kernel<<<(unsigned)((NWI + NWO + 255) / 256), 256>>>(in_proj, out_proj);
    ln_first_kernel<<<TT, 256>>>(x, bres, xnh, xnl, ln_w, ln_b);

    for (int l = 0; l < NLAY; l++) {
        // xz = xn @ Wi^T   (2048 x 3072, K=768), no split
        gemm_tc2_kernel<<<dim3((2 * DIN) / 128, TT / 128, 1), 256,
                          NSTAGE * STAGE_BYTES>>>(
            xnh, xnl,
            wih + (size_t)l * 2 * DIN * DD, wil + (size_t)l * 2 * DIN * DD,
            bxz, 2 * DIN, DD, DD, 0);
        // xc = silu(conv(xi) + cb)
        conv_kernel<<<(TT * DIN / 4) / 256, 256>>>(
            bxz, bxc, conv_w + (size_t)l * DIN * KCC, conv_b + (size_t)l * DIN);
        // dbc = xc @ Wx^T  (split-K x4 + reduce)
        gemm_xproj_kernel<<<dim3(NR / 16, TT / 64, XK), 256>>>(
            bxc, x_proj + (size_t)l * NR * DIN);
        xproj_reduce_kernel<<<(TT * NR + 255) / 256, 256>>>(bdbc);
        // dt = softplus(dbc[:, :48] @ Wdt^T + bdt)
        gemm_dt_kernel<<<dim3(DIN / 64, TT / 128), 256>>>(
            bdbc, NR, dt_w + (size_t)l * DIN * DRR, dt_b + (size_t)l * DIN,
            bdt, DIN, DIN, DRR);
        // chunked selective scan
        scan_p1_kernel<<<dim3(BB * (DIN / 16), CH), 256>>>(
            bdt, bxc, bdbc, A_log + (size_t)l * DIN * NSS);
        scan_chain_kernel<<<(NSTATE + 255) / 256, 256>>>();
        scan_p2_kernel<<<dim3(BB * (DIN / 16), CH), 256>>>(
            bdt, bxc, bdbc, bxz, yh, yl,
            A_log + (size_t)l * DIN * NSS, D_skip + (size_t)l * DIN);
        // x_next partials = y @ Wo^T  split-K x3 (288 CTAs)
        gemm_tc2_kernel<<<dim3(DD / 128, TT / 128, OK), 256,
                          NSTAGE * STAGE_BYTES>>>(
            yh, yl,
            woh + (size_t)l * DD * DIN, wol + (size_t)l * DD * DIN,
            xfpart, DD, OKS, DIN, (size_t)TT * DD);
        // fused reduce + LN (next layer) or final LN
        if (l + 1 < NLAY) {
            ln_fuse_kernel<<<TT, 256>>>(bres, xnh, xnl,
                                        ln_w + (size_t)(l + 1) * DD,
                                        ln_b + (size_t)(l + 1) * DD);
        } else {
            final_fuse_kernel<<<TT, 256>>>(bres, fn_w, fn_b, out);
        }
    }
}

// round 9
// speedup vs baseline: 2.0136x; 1.0155x over previous
#include <cuda_runtime.h>
#include <cuda_bf16.h>
#include <math.h>
#include <stdint.h>

// Problem constants
constexpr int BB   = 2;
constexpr int LL   = 1024;
constexpr int DD   = 768;
constexpr int NLAY = 8;
constexpr int DIN  = 1536;       // 2*D
constexpr int NSS  = 16;
constexpr int DRR  = 48;         // D/16
constexpr int KCC  = 4;
constexpr int TT   = BB * LL;    // 2048 tokens
constexpr int NR   = DRR + 2 * NSS;  // 80 (logical; stored with ld 128)
constexpr int NRP  = 128;        // padded dbc row stride

// Chunked scan
constexpr int CH = 16;
constexpr int CS = LL / CH;      // 64
constexpr int NSTATE = BB * DIN * NSS;   // 49152

// x_proj split-K (tensor core)
constexpr int XK = 8;
constexpr int XKS = DIN / XK;    // 192

// out_proj split-K
constexpr int OK = 3;
constexpr int OKS = DIN / OK;    // 512

// dt padded K
constexpr int DTK = 64;

// fp32 scratch
constexpr size_t O_RES = 0;
constexpr size_t O_XZ  = O_RES + (size_t)TT * DD;
constexpr size_t O_XC  = O_XZ  + (size_t)TT * 2 * DIN;
constexpr size_t O_DT  = O_XC  + (size_t)TT * DIN;
constexpr size_t O_END = O_DT  + (size_t)TT * DIN;
__device__ float g_buf[O_END];

__device__ float g_hend[(size_t)CH * NSTATE];
__device__ float g_P[(size_t)CH * NSTATE];
__device__ float g_hinit[(size_t)CH * NSTATE];
__device__ float g_xf_part[OK][(size_t)TT * DD];
__device__ float g_xp_part[XK][(size_t)TT * NRP];
__device__ float g_dbc[(size_t)TT * NRP];

// bf16 hi/lo activation + weight buffers
constexpr size_t NWI  = (size_t)NLAY * 2 * DIN * DD;      // in_proj
constexpr size_t NWO  = (size_t)NLAY * DD * DIN;          // out_proj
constexpr size_t NWX  = (size_t)NLAY * NRP * DIN;         // x_proj padded
constexpr size_t NWDT = (size_t)NLAY * DIN * DTK;         // dt_w padded
__device__ __nv_bfloat16 g_xn_h[(size_t)TT * DD];
__device__ __nv_bfloat16 g_xn_l[(size_t)TT * DD];
__device__ __nv_bfloat16 g_y_h[(size_t)TT * DIN];
__device__ __nv_bfloat16 g_y_l[(size_t)TT * DIN];
__device__ __nv_bfloat16 g_xc_h[(size_t)TT * DIN];
__device__ __nv_bfloat16 g_xc_l[(size_t)TT * DIN];
__device__ __nv_bfloat16 g_dtA_h[(size_t)TT * DTK];
__device__ __nv_bfloat16 g_dtA_l[(size_t)TT * DTK];
__device__ __nv_bfloat16 g_wi_h[NWI];
__device__ __nv_bfloat16 g_wi_l[NWI];
__device__ __nv_bfloat16 g_wo_h[NWO];
__device__ __nv_bfloat16 g_wo_l[NWO];
__device__ __nv_bfloat16 g_wx_h[NWX];
__device__ __nv_bfloat16 g_wx_l[NWX];
__device__ __nv_bfloat16 g_wdt_h[NWDT];
__device__ __nv_bfloat16 g_wdt_l[NWDT];

// ---------------------------------------------------------------------------
// weight conversion: fp32 -> bf16 hi/lo (once per launch)
// ---------------------------------------------------------------------------
__device__ __forceinline__ void split_store(float v, __nv_bfloat16* H,
                                            __nv_bfloat16* L, size_t i) {
    __nv_bfloat16 h = __float2bfloat16(v);
    H[i] = h;
    L[i] = __float2bfloat16(v - __bfloat162float(h));
}

__global__ void cvt_weights_kernel(const float* __restrict__ wi,
                                   const float* __restrict__ wo,
                                   const float* __restrict__ wx,
                                   const float* __restrict__ wdt) {
    size_t i = (size_t)blockIdx.x * 256 + threadIdx.x;
    if (i < NWI) {
        split_store(wi[i], g_wi_h, g_wi_l, i);
        return;
    }
    i -= NWI;
    if (i < NWO) {
        split_store(wo[i], g_wo_h, g_wo_l, i);
        return;
    }
    i -= NWO;
    if (i < NWX) {
        // dest [l][r(128)][k(1536)]; src [l][r(80)][k]
        size_t k = i % DIN;
        size_t r = (i / DIN) % NRP;
        size_t l = i / ((size_t)DIN * NRP);
        float v = (r < NR) ? wx[(l * NR + r) * DIN + k] : 0.f;
        split_store(v, g_wx_h, g_wx_l, i);
        return;
    }
    i -= NWX;
    if (i < NWDT) {
        // dest [l][d(1536)][k(64)]; src [l][d][k(48)]
        size_t k = i % DTK;
        size_t d = (i / DTK) % DIN;
        size_t l = i / ((size_t)DTK * DIN);
        float v = (k < DRR) ? wdt[(l * DIN + d) * DRR + k] : 0.f;
        split_store(v, g_wdt_h, g_wdt_l, i);
    }
}

// ---------------------------------------------------------------------------
// Warp-shuffle block reduction helper (256 threads / 8 warps)
// ---------------------------------------------------------------------------
__device__ __forceinline__ float block_sum_256(float v, float* red,
                                               int lane, int wid) {
#pragma unroll
    for (int o = 16; o > 0; o >>= 1)
        v += __shfl_xor_sync(0xffffffffu, v, o);
    if (lane == 0) red[wid] = v;
    __syncthreads();
    return red[0] + red[1] + red[2] + red[3] +
           red[4] + red[5] + red[6] + red[7];
}

__device__ __forceinline__ void ln_emit(float d0, float d1, float d2, float inv,
                                        int tid, size_t rowoff,
                                        const float* __restrict__ w,
                                        const float* __restrict__ b,
                                        __nv_bfloat16* __restrict__ xnh,
                                        __nv_bfloat16* __restrict__ xnl) {
#pragma unroll
    for (int c = 0; c < 3; c++) {
        int i = tid + c * 256;
        float dv = (c == 0 ? d0 : c == 1 ? d1 : d2);
        float v = dv * inv * w[i] + b[i];
        __nv_bfloat16 h = __float2bfloat16(v);
        xnh[rowoff + i] = h;
        xnl[rowoff + i] = __float2bfloat16(v - __bfloat162float(h));
    }
}

// ---------------------------------------------------------------------------
// Layer-0 LN: reads input x; res = x; xn = LN(x) -> bf16 hi/lo
// ---------------------------------------------------------------------------
__global__ void __launch_bounds__(256)
ln_first_kernel(const float* __restrict__ x, float* __restrict__ res,
                __nv_bfloat16* __restrict__ xnh, __nv_bfloat16* __restrict__ xnl,
                const float* __restrict__ w, const float* __restrict__ b) {
    int row = blockIdx.x;
    size_t ro = (size_t)row * DD;
    int tid = threadIdx.x;
    int lane = tid & 31, wid = tid >> 5;
    __shared__ float red[8];

    float v0 = x[ro + tid], v1 = x[ro + tid + 256], v2 = x[ro + tid + 512];
    float mu = block_sum_256(v0 + v1 + v2, red, lane, wid) * (1.f / DD);
    __syncthreads();
    float d0 = v0 - mu, d1 = v1 - mu, d2 = v2 - mu;
    float var = block_sum_256(d0 * d0 + d1 * d1 + d2 * d2, red, lane, wid)
                * (1.f / DD);
    float inv = rsqrtf(var + 1e-5f);
    ln_emit(d0, d1, d2, inv, tid, ro, w, b, xnh, xnl);
    res[ro + tid]       = v0;
    res[ro + tid + 256] = v1;
    res[ro + tid + 512] = v2;
}

// ---------------------------------------------------------------------------
// Fused out_proj reduce + next-layer LN
// ---------------------------------------------------------------------------
__global__ void __launch_bounds__(256)
ln_fuse_kernel(float* __restrict__ res,
               __nv_bfloat16* __restrict__ xnh, __nv_bfloat16* __restrict__ xnl,
               const float* __restrict__ w, const float* __restrict__ b) {
    int row = blockIdx.x;
    size_t ro = (size_t)row * DD;
    int tid = threadIdx.x;
    int lane = tid & 31, wid = tid >> 5;
    __shared__ float red[8];

    float v0 = g_xf_part[0][ro + tid] + g_xf_part[1][ro + tid] +
               g_xf_part[2][ro + tid];
    float v1 = g_xf_part[0][ro + tid + 256] + g_xf_part[1][ro + tid + 256] +
               g_xf_part[2][ro + tid + 256];
    float v2 = g_xf_part[0][ro + tid + 512] + g_xf_part[1][ro + tid + 512] +
               g_xf_part[2][ro + tid + 512];
    float mu = block_sum_256(v0 + v1 + v2, red, lane, wid) * (1.f / DD);
    __syncthreads();
    float d0 = v0 - mu, d1 = v1 - mu, d2 = v2 - mu;
    float var = block_sum_256(d0 * d0 + d1 * d1 + d2 * d2, red, lane, wid)
                * (1.f / DD);
    float inv = rsqrtf(var + 1e-5f);
    ln_emit(d0, d1, d2, inv, tid, ro, w, b, xnh, xnl);
    res[ro + tid]       += v0;
    res[ro + tid + 256] += v1;
    res[ro + tid + 512] += v2;
}

// ---------------------------------------------------------------------------
// Final fused: v = sum partials + res; out = LN(v)*fw + fb
// ---------------------------------------------------------------------------
__global__ void __launch_bounds__(256)
final_fuse_kernel(const float* __restrict__ res,
                  const float* __restrict__ w, const float* __restrict__ b,
                  float* __restrict__ out) {
    int row = blockIdx.x;
    size_t ro = (size_t)row * DD;
    int tid = threadIdx.x;
    int lane = tid & 31, wid = tid >> 5;
    __shared__ float red[8];

    float v0 = g_xf_part[0][ro + tid] + g_xf_part[1][ro + tid] +
               g_xf_part[2][ro + tid] + res[ro + tid];
    float v1 = g_xf_part[0][ro + tid + 256] + g_xf_part[1][ro + tid + 256] +
               g_xf_part[2][ro + tid + 256] + res[ro + tid + 256];
    float v2 = g_xf_part[0][ro + tid + 512] + g_xf_part[1][ro + tid + 512] +
               g_xf_part[2][ro + tid + 512] + res[ro + tid + 512];
    float mu = block_sum_256(v0 + v1 + v2, red, lane, wid) * (1.f / DD);
    __syncthreads();
    float d0 = v0 - mu, d1 = v1 - mu, d2 = v2 - mu;
    float var = block_sum_256(d0 * d0 + d1 * d1 + d2 * d2, red, lane, wid)
                * (1.f / DD);
    float inv = rsqrtf(var + 1e-5f);
    out[ro + tid]       = d0 * inv * w[tid]       + b[tid];
    out[ro + tid + 256] = d1 * inv * w[tid + 256] + b[tid + 256];
    out[ro + tid + 512] = d2 * inv * w[tid + 512] + b[tid + 512];
}

// ===========================================================================
// Tensor-core GEMM (bf16 hi/lo, 3-pass), optional split-K + epilogue.
// CTA 128x128, BK=32, 256 thr (8 warps 2Mx4N, warp 64x32), 3-stage cp.async.
// EPI 0: plain store.  EPI 1: bias + softplus.
// ===========================================================================
__device__ __forceinline__ unsigned smem_u32(const void* p) {
    return (unsigned)__cvta_generic_to_shared(p);
}
__device__ __forceinline__ unsigned swz(int r, int c) {
    return (unsigned)(r * 64) + ((((unsigned)c >> 3) ^ (((unsigned)r >> 1) & 3u)) << 4);
}
__device__ __forceinline__ void ldsm_x4(unsigned* r, unsigned addr) {
    asm volatile("ldmatrix.sync.aligned.m8n8.x4.shared.b16 {%0,%1,%2,%3}, [%4];"
                 : "=r"(r[0]), "=r"(r[1]), "=r"(r[2]), "=r"(r[3]) : "r"(addr));
}
__device__ __forceinline__ void mma_bf16(float* c, const unsigned* a, const unsigned* b) {
    asm volatile(
        "mma.sync.aligned.m16n8k16.row.col.f32.bf16.bf16.f32 "
        "{%0,%1,%2,%3}, {%4,%5,%6,%7}, {%8,%9}, {%0,%1,%2,%3};"
        : "+f"(c[0]), "+f"(c[1]), "+f"(c[2]), "+f"(c[3])
        : "r"(a[0]), "r"(a[1]), "r"(a[2]), "r"(a[3]), "r"(b[0]), "r"(b[1]));
}
__device__ __forceinline__ void cp16(unsigned dst, const void* src) {
    asm volatile("cp.async.cg.shared.global [%0], [%1], 16;" :: "r"(dst), "l"(src));
}
__device__ __forceinline__ float softplus_f(float v) {
    return (v > 20.f) ? v : log1pf(__expf(v));
}

constexpr int STAGE_BYTES = 32768;
constexpr int NSTAGE = 3;
constexpr int ARR_A_H = 0, ARR_A_L = 8192, ARR_W_H = 16384, ARR_W_L = 24576;

template <int EPI>
__global__ void __launch_bounds__(256)
gemm_tc2_kernel(const __nv_bfloat16* __restrict__ Ahg,
                const __nv_bfloat16* __restrict__ Alg,
                const __nv_bfloat16* __restrict__ Whg,
                const __nv_bfloat16* __restrict__ Wlg,
                const float* __restrict__ bias,
                float* __restrict__ C, int ldc,
                int Ksplit, int Kfull, size_t partStride) {
    extern __shared__ __align__(16) unsigned char smraw[];
    const unsigned sbase = smem_u32(smraw);

    const int tid  = threadIdx.x;
    const int lane = tid & 31;
    const int warp = tid >> 5;
    const int wm = (warp & 1) * 64;
    const int wn = (warp >> 1) * 32;
    const int m0 = blockIdx.y * 128;
    const int n0 = blockIdx.x * 128;
    const int koff = blockIdx.z * Ksplit;
    float* Cout = C + (size_t)blockIdx.z * partStride;

    const int lrow = tid >> 1;
    const int lq0  = (tid & 1) * 2;
    const size_t aoff = (size_t)(m0 + lrow) * Kfull + koff;
    const size_t woff = (size_t)(n0 + lrow) * Kfull + koff;
    const unsigned sdst0 = (unsigned)(lrow * 64) +
                           (((unsigned)lq0 ^ (((unsigned)lrow >> 1) & 3u)) << 4);
    const unsigned sdst1 = (unsigned)(lrow * 64) +
                           ((((unsigned)lq0 + 1u) ^ (((unsigned)lrow >> 1) & 3u)) << 4);

    const int nsteps = Ksplit / 32;

    auto load_stage = [&](int buf, int k0) {
        unsigned sb = sbase + buf * STAGE_BYTES;
        const __nv_bfloat16* pa_h = Ahg + aoff + k0 + lq0 * 8;
        const __nv_bfloat16* pa_l = Alg + aoff + k0 + lq0 * 8;
        const __nv_bfloat16* pw_h = Whg + woff + k0 + lq0 * 8;
        const __nv_bfloat16* pw_l = Wlg + woff + k0 + lq0 * 8;
        cp16(sb + ARR_A_H + sdst0, pa_h);
        cp16(sb + ARR_A_H + sdst1, pa_h + 8);
        cp16(sb + ARR_A_L + sdst0, pa_l);
        cp16(sb + ARR_A_L + sdst1, pa_l + 8);
        cp16(sb + ARR_W_H + sdst0, pw_h);
        cp16(sb + ARR_W_H + sdst1, pw_h + 8);
        cp16(sb + ARR_W_L + sdst0, pw_l);
        cp16(sb + ARR_W_L + sdst1, pw_l + 8);
    };

    float acc[4][4][4];
#pragma unroll
    for (int i = 0; i < 4; i++)
#pragma unroll
        for (int j = 0; j < 4; j++)
#pragma unroll
            for (int q = 0; q < 4; q++) acc[i][j][q] = 0.f;

    load_stage(0, 0);
    asm volatile("cp.async.commit_group;");
    if (nsteps > 1) load_stage(1, 32);
    asm volatile("cp.async.commit_group;");

    const int arow = wm + (lane & 7) + (lane & 8);
    const int brow = wn + (lane & 7) + ((lane >> 4) << 3);

    for (int s = 0; s < nsteps; s++) {
        asm volatile("cp.async.wait_group 1;");
        __syncthreads();
        if (s + 2 < nsteps) load_stage((s + 2) % NSTAGE, (s + 2) * 32);
        asm volatile("cp.async.commit_group;");

        const unsigned sb = sbase + (s % NSTAGE) * STAGE_BYTES;
#pragma unroll
        for (int kk = 0; kk < 32; kk += 16) {
            const int acol = kk + ((lane >> 4) << 3);
            const int bcol = kk + (lane & 8);
            unsigned af[4][4];
            unsigned whf[4][2], wlf[4][2];
#pragma unroll
            for (int mi = 0; mi < 4; mi++)
                ldsm_x4(af[mi], sb + ARR_A_H + swz(arow + mi * 16, acol));
#pragma unroll
            for (int nj = 0; nj < 2; nj++) {
                unsigned r[4];
                ldsm_x4(r, sb + ARR_W_H + swz(brow + nj * 16, bcol));
                whf[nj * 2][0] = r[0]; whf[nj * 2][1] = r[1];
                whf[nj * 2 + 1][0] = r[2]; whf[nj * 2 + 1][1] = r[3];
                ldsm_x4(r, sb + ARR_W_L + swz(brow + nj * 16, bcol));
                wlf[nj * 2][0] = r[0]; wlf[nj * 2][1] = r[1];
                wlf[nj * 2 + 1][0] = r[2]; wlf[nj * 2 + 1][1] = r[3];
            }
#pragma unroll
            for (int mi = 0; mi < 4; mi++)
#pragma unroll
                for (int ni = 0; ni < 4; ni++) {
                    mma_bf16(acc[mi][ni], af[mi], whf[ni]);
                    mma_bf16(acc[mi][ni], af[mi], wlf[ni]);
                }
#pragma unroll
            for (int mi = 0; mi < 4; mi++)
                ldsm_x4(af[mi], sb + ARR_A_L + swz(arow + mi * 16, acol));
#pragma unroll
            for (int mi = 0; mi < 4; mi++)
#pragma unroll
                for (int ni = 0; ni < 4; ni++)
                    mma_bf16(acc[mi][ni], af[mi], whf[ni]);
        }
    }

#pragma unroll
    for (int mi = 0; mi < 4; mi++) {
        int r0 = m0 + wm + mi * 16 + (lane >> 2);
#pragma unroll
        for (int ni = 0; ni < 4; ni++) {
            int c = n0 + wn + ni * 8 + (lane & 3) * 2;
            float2 v0 = make_float2(acc[mi][ni][0], acc[mi][ni][1]);
            float2 v1 = make_float2(acc[mi][ni][2], acc[mi][ni][3]);
            if (EPI == 1) {
                float b0 = bias[c], b1 = bias[c + 1];
                v0.x = softplus_f(v0.x + b0); v0.y = softplus_f(v0.y + b1);
                v1.x = softplus_f(v1.x + b0); v1.y = softplus_f(v1.y + b1);
            }
            *(float2*)&Cout[(size_t)r0 * ldc + c] = v0;
            *(float2*)&Cout[(size_t)(r0 + 8) * ldc + c] = v1;
        }
    }
}

// ---------------------------------------------------------------------------
// x_proj reduce: dbc = sum of XK partials; emit dt-input bf16 hi/lo (cols<64)
// ---------------------------------------------------------------------------
__global__ void __launch_bounds__(256)
xred_kernel(float* __restrict__ dbc) {
    int i = blockIdx.x * 256 + threadIdx.x;
    if (i >= TT * NRP) return;
    float s = 0.f;
#pragma unroll
    for (int k = 0; k < XK; k++) s += g_xp_part[k][i];
    dbc[i] = s;
    int col = i & (NRP - 1);
    int row = i >> 7;
    if (col < DTK) {
        float v = (col < DRR) ? s : 0.f;
        split_store(v, g_dtA_h, g_dtA_l, (size_t)row * DTK + col);
    }
}

// ---------------------------------------------------------------------------
// Causal depthwise conv (KC=4, left pad 3) + bias + SiLU.
// Emits fp32 xc (for scan) and bf16 hi/lo (for x_proj TC GEMM).
// ---------------------------------------------------------------------------
__global__ void __launch_bounds__(256)
conv_kernel(const float* __restrict__ xz, float* __restrict__ xc,
            __nv_bfloat16* __restrict__ xch, __nv_bfloat16* __restrict__ xcl,
            const float* __restrict__ cw, const float* __restrict__ cb) {
    int idx = blockIdx.x * blockDim.x + threadIdx.x;
    if (idx >= TT * DIN / 4) return;
    int c4 = (idx % (DIN / 4)) * 4;
    int tb = idx / (DIN / 4);
    int t = tb % LL;
    int b = tb / LL;
    float4 acc = *(const float4*)(cb + c4);
    float4 w0 = *(const float4*)(cw + (c4 + 0) * KCC);
    float4 w1 = *(const float4*)(cw + (c4 + 1) * KCC);
    float4 w2 = *(const float4*)(cw + (c4 + 2) * KCC);
    float4 w3 = *(const float4*)(cw + (c4 + 3) * KCC);
    const float wk0[4] = {w0.x, w0.y, w0.z, w0.w};
    const float wk1[4] = {w1.x, w1.y, w1.z, w1.w};
    const float wk2[4] = {w2.x, w2.y, w2.z, w2.w};
    const float wk3[4] = {w3.x, w3.y, w3.z, w3.w};
#pragma unroll
    for (int k = 0; k < KCC; k++) {
        int tt = t - (KCC - 1) + k;
        if (tt >= 0) {
            float4 xv = *(const float4*)(
                xz + ((size_t)(b * LL + tt)) * (2 * DIN) + c4);
            acc.x += wk0[k] * xv.x;
            acc.y += wk1[k] * xv.y;
            acc.z += wk2[k] * xv.z;
            acc.w += wk3[k] * xv.w;
        }
    }
    acc.x = acc.x / (1.f + __expf(-acc.x));
    acc.y = acc.y / (1.f + __expf(-acc.y));
    acc.z = acc.z / (1.f + __expf(-acc.z));
    acc.w = acc.w / (1.f + __expf(-acc.w));
    size_t o = (size_t)tb * DIN + c4;
    *(float4*)(xc + o) = acc;
    split_store(acc.x, xch, xcl, o);
    split_store(acc.y, xch, xcl, o + 1);
    split_store(acc.z, xch, xcl, o + 2);
    split_store(acc.w, xch, xcl, o + 3);
}

// ===========================================================================
// Chunked selective scan (3 phases), CH=16, CS=64. dbc has row stride 128.
// ===========================================================================
__global__ void __launch_bounds__(256)
scan_p1_kernel(const float* __restrict__ dt, const float* __restrict__ xc,
               const float* __restrict__ dbc, const float* __restrict__ Alog) {
    int warp = threadIdx.x >> 5;
    int lane = threadIdx.x & 31;
    int n = lane & 15;
    int dl = lane >> 4;
    constexpr int BLOCKS_PER_B = DIN / 16;
    int b = blockIdx.x / BLOCKS_PER_B;
    int d = (blockIdx.x % BLOCKS_PER_B) * 16 + warp * 2 + dl;
    int c = blockIdx.y;

    float Av = -__expf(Alog[d * NSS + n]);
    float h = 0.f, sdt = 0.f;
    size_t rowbase = (size_t)b * LL + (size_t)c * CS;

    for (int t = 0; t < CS; t++) {
        size_t row = rowbase + t;
        float dtv = dt[row * DIN + d];
        float xv  = xc[row * DIN + d];
        float Bv  = dbc[row * NRP + DRR + n];
        sdt += dtv;
        h = __expf(dtv * Av) * h + (dtv * xv) * Bv;
    }
    int idx = (b * DIN + d) * NSS + n;
    g_hend[(size_t)c * NSTATE + idx] = h;
    g_P[(size_t)c * NSTATE + idx]   = __expf(Av * sdt);
}

__global__ void __launch_bounds__(256)
scan_chain_kernel() {
    int i = blockIdx.x * 256 + threadIdx.x;
    if (i >= NSTATE) return;
    float hin = 0.f;
#pragma unroll
    for (int c = 0; c < CH; c++) {
        g_hinit[(size_t)c * NSTATE + i] = hin;
        hin = g_P[(size_t)c * NSTATE + i] * hin + g_hend[(size_t)c * NSTATE + i];
    }
}

__global__ void __launch_bounds__(256)
scan_p2_kernel(const float* __restrict__ dt, const float* __restrict__ xc,
               const float* __restrict__ dbc, const float* __restrict__ xz,
               __nv_bfloat16* __restrict__ yh, __nv_bfloat16* __restrict__ yl,
               const float* __restrict__ Alog, const float* __restrict__ Dp) {
    int warp = threadIdx.x >> 5;
    int lane = threadIdx.x & 31;
    int n = lane & 15;
    int dl = lane >> 4;
    constexpr int BLOCKS_PER_B = DIN / 16;
    int b = blockIdx.x / BLOCKS_PER_B;
    int d = (blockIdx.x % BLOCKS_PER_B) * 16 + warp * 2 + dl;
    int c = blockIdx.y;

    float Av = -__expf(Alog[d * NSS + n]);
    float Dv = Dp[d];
    int idx = (b * DIN + d) * NSS + n;
    float h = g_hinit[(size_t)c * NSTATE + idx];
    size_t rowbase = (size_t)b * LL + (size_t)c * CS;

    for (int t = 0; t < CS; t++) {
        size_t row = rowbase + t;
        float dtv = dt[row * DIN + d];
        float xv  = xc[row * DIN + d];
        float Bv  = dbc[row * NRP + DRR + n];
        float Cv  = dbc[row * NRP + DRR + NSS + n];
        h = __expf(dtv * Av) * h + (dtv * xv) * Bv;
        float yp = h * Cv;
        yp += __shfl_xor_sync(0xffffffffu, yp, 8);
        yp += __shfl_xor_sync(0xffffffffu, yp, 4);
        yp += __shfl_xor_sync(0xffffffffu, yp, 2);
        yp += __shfl_xor_sync(0xffffffffu, yp, 1);
        if (n == 0) {
            float zv = xz[row * (2 * DIN) + DIN + d];
            float sg = zv / (1.f + __expf(-zv));
            float g = (yp + xv * Dv) * sg;
            __nv_bfloat16 gh = __float2bfloat16(g);
            yh[row * DIN + d] = gh;
            yl[row * DIN + d] = __float2bfloat16(g - __bfloat162float(gh));
        }
    }
}

// ---------------------------------------------------------------------------
// Orchestration
// ---------------------------------------------------------------------------
extern "C" void kernel_launch(void* const* d_in, const int* in_sizes, int n_in,
                              void* d_out, int out_size) {
    const float* x        = (const float*)d_in[0];
    const float* ln_w     = (const float*)d_in[1];
    const float* ln_b     = (const float*)d_in[2];
    const float* in_proj  = (const float*)d_in[3];
    const float* conv_w   = (const float*)d_in[4];
    const float* conv_b   = (const float*)d_in[5];
    const float* x_proj   = (const float*)d_in[6];
    const float* dt_w     = (const float*)d_in[7];
    const float* dt_b     = (const float*)d_in[8];
    const float* A_log    = (const float*)d_in[9];
    const float* D_skip   = (const float*)d_in[10];
    const float* out_proj = (const float*)d_in[11];
    const float* fn_w     = (const float*)d_in[12];
    const float* fn_b     = (const float*)d_in[13];
    float* out = (float*)d_out;

    float* base = nullptr;
    cudaGetSymbolAddress((void**)&base, g_buf);
    float* bres = base + O_RES;
    float* bxz  = base + O_XZ;
    float* bxc  = base + O_XC;
    float* bdt  = base + O_DT;

    __nv_bfloat16 *xnh, *xnl, *yh, *yl, *xch, *xcl, *dtah, *dtal;
    __nv_bfloat16 *wih, *wil, *woh, *wol, *wxh, *wxl, *wdh, *wdl;
    cudaGetSymbolAddress((void**)&xnh, g_xn_h);
    cudaGetSymbolAddress((void**)&xnl, g_xn_l);
    cudaGetSymbolAddress((void**)&yh,  g_y_h);
    cudaGetSymbolAddress((void**)&yl,  g_y_l);
    cudaGetSymbolAddress((void**)&xch, g_xc_h);
    cudaGetSymbolAddress((void**)&xcl, g_xc_l);
    cudaGetSymbolAddress((void**)&dtah, g_dtA_h);
    cudaGetSymbolAddress((void**)&dtal, g_dtA_l);
    cudaGetSymbolAddress((void**)&wih, g_wi_h);
    cudaGetSymbolAddress((void**)&wil, g_wi_l);
    cudaGetSymbolAddress((void**)&woh, g_wo_h);
    cudaGetSymbolAddress((void**)&wol, g_wo_l);
    cudaGetSymbolAddress((void**)&wxh, g_wx_h);
    cudaGetSymbolAddress((void**)&wxl, g_wx_l);
    cudaGetSymbolAddress((void**)&wdh, g_wdt_h);
    cudaGetSymbolAddress((void**)&wdl, g_wdt_l);

    float *xfpart, *xppart, *bdbc;
    cudaGetSymbolAddress((void**)&xfpart, g_xf_part);
    cudaGetSymbolAddress((void**)&xppart, g_xp_part);
    cudaGetSymbolAddress((void**)&bdbc, g_dbc);

    cudaFuncSetAttribute(gemm_tc2_kernel<0>,
                         cudaFuncAttributeMaxDynamicSharedMemorySize,
                         NSTAGE * STAGE_BYTES);
    cudaFuncSetAttribute(gemm_tc2_kernel<1>,
                         cudaFuncAttributeMaxDynamicSharedMemorySize,
                         NSTAGE * STAGE_BYTES);

    size_t ncvt = NWI + NWO + NWX + NWDT;
    cvt_weights_kernel<<<(unsigned)((ncvt + 255) / 256), 256>>>(
        in_proj, out_proj, x_proj, dt_w);
    ln_first_kernel<<<TT, 256>>>(x, bres, xnh, xnl, ln_w, ln_b);

    for (int l = 0; l < NLAY; l++) {
        // xz = xn @ Wi^T   (2048 x 3072, K=768)
        gemm_tc2_kernel<0><<<dim3((2 * DIN) / 128, TT / 128, 1), 256,
                             NSTAGE * STAGE_BYTES>>>(
            xnh, xnl,
            wih + (size_t)l * 2 * DIN * DD, wil + (size_t)l * 2 * DIN * DD,
            nullptr, bxz, 2 * DIN, DD, DD, 0);
        // xc = silu(conv(xi) + cb)  (fp32 + bf16 hi/lo)
        conv_kernel<<<(TT * DIN / 4) / 256, 256>>>(
            bxz, bxc, xch, xcl,
            conv_w + (size_t)l * DIN * KCC, conv_b + (size_t)l * DIN);
        // dbc partials = xc @ Wx^T  (TC, N padded 128, split-K x8)
        gemm_tc2_kernel<0><<<dim3(1, TT / 128, XK), 256,
                             NSTAGE * STAGE_BYTES>>>(
            xch, xcl,
            wxh + (size_t)l * NRP * DIN, wxl + (size_t)l * NRP * DIN,
            nullptr, xppart, NRP, XKS, DIN, (size_t)TT * NRP);
        // reduce -> dbc fp32 + dt-input bf16 hi/lo
        xred_kernel<<<(TT * NRP) / 256, 256>>>(bdbc);
        // dt = softplus(dtA @ Wdt^T + bdt)  (TC, K=64 padded)
        gemm_tc2_kernel<1><<<dim3(DIN / 128, TT / 128, 1), 256,
                             NSTAGE * STAGE_BYTES>>>(
            dtah, dtal,
            wdh + (size_t)l * DIN * DTK, wdl + (size_t)l * DIN * DTK,
            dt_b + (size_t)l * DIN, bdt, DIN, DTK, DTK, 0);
        // chunked selective scan
        scan_p1_kernel<<<dim3(BB * (DIN / 16), CH), 256>>>(
            bdt, bxc, bdbc, A_log + (size_t)l * DIN * NSS);
        scan_chain_kernel<<<(NSTATE + 255) / 256, 256>>>();
        scan_p2_kernel<<<dim3(BB * (DIN / 16), CH), 256>>>(
            bdt, bxc, bdbc, bxz, yh, yl,
            A_log + (size_t)l * DIN * NSS, D_skip + (size_t)l * DIN);
        // x_next partials = y @ Wo^T  split-K x3
        gemm_tc2_kernel<0><<<dim3(DD / 128, TT / 128, OK), 256,
                             NSTAGE * STAGE_BYTES>>>(
            yh, yl,
            woh + (size_t)l * DD * DIN, wol + (size_t)l * DD * DIN,
            nullptr, xfpart, DD, OKS, DIN, (size_t)TT * DD);
        // fused reduce + LN (next layer) or final LN
        if (l + 1 < NLAY) {
            ln_fuse_kernel<<<TT, 256>>>(bres, xnh, xnl,
                                        ln_w + (size_t)(l + 1) * DD,
                                        ln_b + (size_t)(l + 1) * DD);
        } else {
            final_fuse_kernel<<<TT, 256>>>(bres, fn_w, fn_b, out);
        }
    }
}